// round 1
// baseline (speedup 1.0000x reference)
#include <cuda_runtime.h>
#include <math.h>

// Problem constants (fixed shapes per setup_inputs)
#define BATCH 16
#define CIN   256
#define CTOT  512
#define DDIM  512
#define LSP   4096
#define UTOP  450
#define SCALE 0.044194173824159216f   // 1/sqrt(512)

// ---------------------------------------------------------------------------
// Scratch (device globals: allocation inside kernel_launch is forbidden)
// ---------------------------------------------------------------------------
__device__ float g_QKV[BATCH * 3 * DDIM * LSP];     // [b][m in 0..1536)[sp]  (Q|K|V stacked)
__device__ float g_Ks[BATCH * UTOP * DDIM];          // gathered K_sample rows
__device__ float g_M[BATCH * LSP];                   // sparsity measure
__device__ int   g_selrank[BATCH * LSP];             // l -> rank in top-k, or -1
__device__ int   g_mtop[BATCH * UTOP];               // rank -> l
__device__ float g_Qr[BATCH * UTOP * DDIM];          // gathered Q_reduce rows
__device__ float g_Scores[BATCH * UTOP * LSP];       // scores / attn (in place softmax)
__device__ float g_Upd[BATCH * UTOP * DDIM];         // attn @ V
__device__ float g_Vpart[BATCH * 4 * DDIM];          // partial V sums
__device__ float g_Vmean[BATCH * DDIM];              // V mean over L

// ---------------------------------------------------------------------------
// 1) Projection GEMM: Y[b, m, sp] = sum_c W[m%512, c] * X[b, c, sp] + bias
//    m in [0,1536): 0..511 -> Q (Wq), 512..1023 -> K, 1024..1535 -> V
//    X = concat(input_1, input_2) along c.
//    BM=128, BN=128, BK=16, 256 threads, 8x8 per-thread tile.
// ---------------------------------------------------------------------------
__global__ __launch_bounds__(256) void proj_kernel(
    const float* __restrict__ in1, const float* __restrict__ in2,
    const float* __restrict__ Wq, const float* __restrict__ bq,
    const float* __restrict__ Wk, const float* __restrict__ bk,
    const float* __restrict__ Wv, const float* __restrict__ bv) {
  const int b  = blockIdx.z;
  const int m0 = blockIdx.y * 128;           // 0..1535
  const int n0 = blockIdx.x * 128;           // spatial
  const int wsel = m0 >> 9;
  const float* W    = (wsel == 0) ? Wq : (wsel == 1) ? Wk : Wv;
  const float* bias = (wsel == 0) ? bq : (wsel == 1) ? bk : bv;
  const int mrow0 = m0 & 511;

  __shared__ float As[16][128];
  __shared__ float Bs[16][128];

  const int tid = threadIdx.x;
  const int tx = tid & 15, ty = tid >> 4;
  float acc[8][8] = {};

  const float* x1 = in1 + (size_t)b * CIN * LSP;
  const float* x2 = in2 + (size_t)b * CIN * LSP;

  for (int kt = 0; kt < 512; kt += 16) {
    // As[k][m] = W[mrow0+m][kt+k] (transpose on store)
    #pragma unroll
    for (int i = 0; i < 2; i++) {
      int f = tid * 2 + i;
      int m = f >> 2, kq = (f & 3) * 4;
      float4 v = *(const float4*)(W + (size_t)(mrow0 + m) * 512 + kt + kq);
      As[kq + 0][m] = v.x; As[kq + 1][m] = v.y;
      As[kq + 2][m] = v.z; As[kq + 3][m] = v.w;
    }
    // Bs[k][n] = X[kt+k][n0+n] (contiguous)
    #pragma unroll
    for (int i = 0; i < 2; i++) {
      int f = tid * 2 + i;
      int k = f >> 5, nq = (f & 31) * 4;
      int c = kt + k;
      const float* src = (c < 256) ? (x1 + (size_t)c * LSP)
                                   : (x2 + (size_t)(c - 256) * LSP);
      *(float4*)&Bs[k][nq] = *(const float4*)(src + n0 + nq);
    }
    __syncthreads();
    #pragma unroll
    for (int k = 0; k < 16; k++) {
      float a[8], bb[8];
      #pragma unroll
      for (int i = 0; i < 8; i++) a[i]  = As[k][ty * 8 + i];
      #pragma unroll
      for (int j = 0; j < 8; j++) bb[j] = Bs[k][tx * 8 + j];
      #pragma unroll
      for (int i = 0; i < 8; i++)
        #pragma unroll
        for (int j = 0; j < 8; j++) acc[i][j] += a[i] * bb[j];
    }
    __syncthreads();
  }

  float* out = g_QKV + (size_t)b * 3 * DDIM * LSP;
  #pragma unroll
  for (int i = 0; i < 8; i++) {
    float bval = bias[mrow0 + ty * 8 + i];
    float* orow = out + (size_t)(m0 + ty * 8 + i) * LSP + n0 + tx * 8;
    #pragma unroll
    for (int j = 0; j < 8; j++) orow[j] = acc[i][j] + bval;
  }
}

// ---------------------------------------------------------------------------
// 2) Gather K_sample rows (K viewed as (L, D) from flat d-major buffer)
// ---------------------------------------------------------------------------
__global__ void gather_ks_kernel(const int* __restrict__ idx) {
  const int b = blockIdx.y, s = blockIdx.x;
  const int l = idx[s];
  const float4* src = (const float4*)(g_QKV + (size_t)b * 3 * DDIM * LSP
                                      + (size_t)DDIM * LSP + (size_t)l * 512);
  float4* dst = (float4*)(g_Ks + ((size_t)b * UTOP + s) * 512);
  dst[threadIdx.x] = src[threadIdx.x];   // 128 threads x float4 = 512 floats
}

// ---------------------------------------------------------------------------
// 3) Fused QKs + M:  M[l] = max_s dot(Q[l],Ks[s]) - (sum_s dot)/4096
//    BM=128 rows, loop s in tiles of 64, BK=16; 256 threads, 8x4 per thread.
// ---------------------------------------------------------------------------
__global__ __launch_bounds__(256) void qks_m_kernel() {
  const int b  = blockIdx.y;
  const int l0 = blockIdx.x * 128;
  const float* Qb = g_QKV + (size_t)b * 3 * DDIM * LSP;   // Q rows: Qb + l*512
  const float* Ks = g_Ks + (size_t)b * UTOP * DDIM;

  __shared__ float As[16][128];
  __shared__ float Bs[16][64];

  const int tid = threadIdx.x;
  const int tx = tid & 15, ty = tid >> 4;
  float rmax[8], rsum[8];
  #pragma unroll
  for (int i = 0; i < 8; i++) { rmax[i] = -3.0e38f; rsum[i] = 0.f; }

  for (int s0 = 0; s0 < UTOP; s0 += 64) {
    float acc[8][4] = {};
    for (int kt = 0; kt < 512; kt += 16) {
      #pragma unroll
      for (int i = 0; i < 2; i++) {
        int f = tid * 2 + i;
        int m = f >> 2, kq = (f & 3) * 4;
        float4 v = *(const float4*)(Qb + (size_t)(l0 + m) * 512 + kt + kq);
        As[kq + 0][m] = v.x; As[kq + 1][m] = v.y;
        As[kq + 2][m] = v.z; As[kq + 3][m] = v.w;
      }
      {
        int n = tid >> 2, kq = (tid & 3) * 4;
        float4 v = make_float4(0.f, 0.f, 0.f, 0.f);
        if (s0 + n < UTOP)
          v = *(const float4*)(Ks + (size_t)(s0 + n) * 512 + kt + kq);
        Bs[kq + 0][n] = v.x; Bs[kq + 1][n] = v.y;
        Bs[kq + 2][n] = v.z; Bs[kq + 3][n] = v.w;
      }
      __syncthreads();
      #pragma unroll
      for (int k = 0; k < 16; k++) {
        float a[8], bb[4];
        #pragma unroll
        for (int i = 0; i < 8; i++) a[i]  = As[k][ty * 8 + i];
        #pragma unroll
        for (int j = 0; j < 4; j++) bb[j] = Bs[k][tx * 4 + j];
        #pragma unroll
        for (int i = 0; i < 8; i++)
          #pragma unroll
          for (int j = 0; j < 4; j++) acc[i][j] += a[i] * bb[j];
      }
      __syncthreads();
    }
    #pragma unroll
    for (int j = 0; j < 4; j++) {
      if (s0 + tx * 4 + j < UTOP) {
        #pragma unroll
        for (int i = 0; i < 8; i++) {
          rmax[i] = fmaxf(rmax[i], acc[i][j]);
          rsum[i] += acc[i][j];
        }
      }
    }
  }
  // reduce across the 16 tx lanes (lanes 0-15 / 16-31 groups within warp)
  #pragma unroll
  for (int off = 8; off; off >>= 1) {
    #pragma unroll
    for (int i = 0; i < 8; i++) {
      rmax[i] = fmaxf(rmax[i], __shfl_xor_sync(0xffffffffu, rmax[i], off));
      rsum[i] += __shfl_xor_sync(0xffffffffu, rsum[i], off);
    }
  }
  if (tx == 0) {
    #pragma unroll
    for (int i = 0; i < 8; i++)
      g_M[b * LSP + l0 + ty * 8 + i] = rmax[i] - rsum[i] * (1.0f / 4096.0f);
  }
}

// ---------------------------------------------------------------------------
// 4) Top-k via per-batch bitonic sort of 4096 64-bit (flipped-value, index)
//    keys. Ascending key sort = descending value, ties lower index first
//    (matches jax.lax.top_k).
// ---------------------------------------------------------------------------
__global__ __launch_bounds__(1024) void topk_kernel() {
  const int b = blockIdx.x;
  __shared__ unsigned long long keys[4096];
  const int tid = threadIdx.x;

  for (int i = tid; i < 4096; i += 1024) {
    unsigned u = __float_as_uint(g_M[b * LSP + i]);
    u = (u & 0x80000000u) ? ~u : (u | 0x80000000u);   // ascending-order map
    keys[i] = ((unsigned long long)(~u) << 32) | (unsigned)i;
  }
  __syncthreads();

  for (int k = 2; k <= 4096; k <<= 1) {
    for (int j = k >> 1; j > 0; j >>= 1) {
      for (int t = tid; t < 4096; t += 1024) {
        int ixj = t ^ j;
        if (ixj > t) {
          unsigned long long a = keys[t], c = keys[ixj];
          bool up = ((t & k) == 0);
          if ((a > c) == up) { keys[t] = c; keys[ixj] = a; }
        }
      }
      __syncthreads();
    }
  }

  for (int i = tid; i < 4096; i += 1024) g_selrank[b * LSP + i] = -1;
  __syncthreads();
  if (tid < UTOP) {
    int l = (int)(unsigned)(keys[tid] & 0xffffffffu);
    g_selrank[b * LSP + l] = tid;
    g_mtop[b * UTOP + tid] = l;
  }
}

// ---------------------------------------------------------------------------
// 5) Gather Q_reduce rows
// ---------------------------------------------------------------------------
__global__ void gather_qr_kernel() {
  const int b = blockIdx.y, u = blockIdx.x;
  const int l = g_mtop[b * UTOP + u];
  const float4* src = (const float4*)(g_QKV + (size_t)b * 3 * DDIM * LSP + (size_t)l * 512);
  float4* dst = (float4*)(g_Qr + ((size_t)b * UTOP + u) * 512);
  dst[threadIdx.x] = src[threadIdx.x];
}

// ---------------------------------------------------------------------------
// 6) scores[b,u,l] = SCALE * dot(Qr[u], K[l]);  BM=64(u) BN=128(l) BK=16
// ---------------------------------------------------------------------------
__global__ __launch_bounds__(256) void scores_kernel() {
  const int b  = blockIdx.z;
  const int u0 = blockIdx.y * 64;
  const int l0 = blockIdx.x * 128;
  const float* Qr = g_Qr + (size_t)b * UTOP * DDIM;
  const float* Kb = g_QKV + (size_t)b * 3 * DDIM * LSP + (size_t)DDIM * LSP;

  __shared__ float As[16][64];
  __shared__ float Bs[16][128];

  const int tid = threadIdx.x;
  const int tx = tid & 15, ty = tid >> 4;
  float acc[4][8] = {};

  for (int kt = 0; kt < 512; kt += 16) {
    {
      int m = tid >> 2, kq = (tid & 3) * 4;
      int row = u0 + m; if (row > UTOP - 1) row = UTOP - 1;
      float4 v = *(const float4*)(Qr + (size_t)row * 512 + kt + kq);
      As[kq + 0][m] = v.x; As[kq + 1][m] = v.y;
      As[kq + 2][m] = v.z; As[kq + 3][m] = v.w;
    }
    #pragma unroll
    for (int i = 0; i < 2; i++) {
      int f = tid * 2 + i;
      int n = f >> 2, kq = (f & 3) * 4;
      float4 v = *(const float4*)(Kb + (size_t)(l0 + n) * 512 + kt + kq);
      Bs[kq + 0][n] = v.x; Bs[kq + 1][n] = v.y;
      Bs[kq + 2][n] = v.z; Bs[kq + 3][n] = v.w;
    }
    __syncthreads();
    #pragma unroll
    for (int k = 0; k < 16; k++) {
      float a[4], bb[8];
      #pragma unroll
      for (int i = 0; i < 4; i++) a[i]  = As[k][ty * 4 + i];
      #pragma unroll
      for (int j = 0; j < 8; j++) bb[j] = Bs[k][tx * 8 + j];
      #pragma unroll
      for (int i = 0; i < 4; i++)
        #pragma unroll
        for (int j = 0; j < 8; j++) acc[i][j] += a[i] * bb[j];
    }
    __syncthreads();
  }
  #pragma unroll
  for (int i = 0; i < 4; i++) {
    int u = u0 + ty * 4 + i;
    if (u < UTOP) {
      float* orow = g_Scores + ((size_t)b * UTOP + u) * LSP + l0 + tx * 8;
      #pragma unroll
      for (int j = 0; j < 8; j++) orow[j] = acc[i][j] * SCALE;
    }
  }
}

// ---------------------------------------------------------------------------
// 7) Row softmax over 4096, in place
// ---------------------------------------------------------------------------
__global__ __launch_bounds__(256) void softmax_kernel() {
  const int row = blockIdx.x;             // b*UTOP + u
  float4* p = (float4*)(g_Scores + (size_t)row * LSP);
  const int tid = threadIdx.x;
  __shared__ float red[256];

  float4 r[4];
  float m = -3.0e38f;
  #pragma unroll
  for (int i = 0; i < 4; i++) {
    r[i] = p[tid + i * 256];
    m = fmaxf(m, fmaxf(fmaxf(r[i].x, r[i].y), fmaxf(r[i].z, r[i].w)));
  }
  red[tid] = m; __syncthreads();
  for (int s = 128; s; s >>= 1) {
    if (tid < s) red[tid] = fmaxf(red[tid], red[tid + s]);
    __syncthreads();
  }
  m = red[0]; __syncthreads();

  float sum = 0.f;
  #pragma unroll
  for (int i = 0; i < 4; i++) {
    r[i].x = expf(r[i].x - m); r[i].y = expf(r[i].y - m);
    r[i].z = expf(r[i].z - m); r[i].w = expf(r[i].w - m);
    sum += r[i].x + r[i].y + r[i].z + r[i].w;
  }
  red[tid] = sum; __syncthreads();
  for (int s = 128; s; s >>= 1) {
    if (tid < s) red[tid] += red[tid + s];
    __syncthreads();
  }
  float inv = 1.0f / red[0];
  #pragma unroll
  for (int i = 0; i < 4; i++) {
    r[i].x *= inv; r[i].y *= inv; r[i].z *= inv; r[i].w *= inv;
    p[tid + i * 256] = r[i];
  }
}

// ---------------------------------------------------------------------------
// 8) V mean over L (two-stage, deterministic)
// ---------------------------------------------------------------------------
__global__ __launch_bounds__(512) void vpart_kernel() {
  const int b = blockIdx.y, g = blockIdx.x;   // g in [0,4)
  const int d = threadIdx.x;
  const float* Vb = g_QKV + (size_t)b * 3 * DDIM * LSP + 2 * (size_t)DDIM * LSP;
  const float* base = Vb + (size_t)(g * 1024) * 512 + d;
  float s0 = 0.f, s1 = 0.f, s2 = 0.f, s3 = 0.f;
  for (int l = 0; l < 1024; l += 4) {
    s0 += base[(size_t)(l + 0) * 512];
    s1 += base[(size_t)(l + 1) * 512];
    s2 += base[(size_t)(l + 2) * 512];
    s3 += base[(size_t)(l + 3) * 512];
  }
  g_Vpart[((size_t)b * 4 + g) * 512 + d] = (s0 + s1) + (s2 + s3);
}

__global__ __launch_bounds__(512) void vmean_kernel() {
  const int b = blockIdx.x, d = threadIdx.x;
  float s = 0.f;
  #pragma unroll
  for (int g = 0; g < 4; g++) s += g_Vpart[((size_t)b * 4 + g) * 512 + d];
  g_Vmean[b * 512 + d] = s * (1.0f / 4096.0f);
}

// ---------------------------------------------------------------------------
// 9) upd[b,u,d] = sum_l attn[u,l] * V[l,d];  BM=64(u) BN=128(d) BK=16, K=4096
// ---------------------------------------------------------------------------
__global__ __launch_bounds__(256) void upd_kernel() {
  const int b  = blockIdx.z;
  const int u0 = blockIdx.y * 64;
  const int n0 = blockIdx.x * 128;
  const float* At = g_Scores + (size_t)b * UTOP * LSP;  // attn rows, stride 4096
  const float* Vb = g_QKV + (size_t)b * 3 * DDIM * LSP + 2 * (size_t)DDIM * LSP;

  __shared__ float As[16][64];
  __shared__ float Bs[16][128];

  const int tid = threadIdx.x;
  const int tx = tid & 15, ty = tid >> 4;
  float acc[4][8] = {};

  for (int kt = 0; kt < 4096; kt += 16) {
    {
      int m = tid >> 2, kq = (tid & 3) * 4;
      int row = u0 + m; if (row > UTOP - 1) row = UTOP - 1;
      float4 v = *(const float4*)(At + (size_t)row * LSP + kt + kq);
      As[kq + 0][m] = v.x; As[kq + 1][m] = v.y;
      As[kq + 2][m] = v.z; As[kq + 3][m] = v.w;
    }
    #pragma unroll
    for (int i = 0; i < 2; i++) {
      int f = tid * 2 + i;
      int k = f >> 5, nq = (f & 31) * 4;
      *(float4*)&Bs[k][nq] = *(const float4*)(Vb + (size_t)(kt + k) * 512 + n0 + nq);
    }
    __syncthreads();
    #pragma unroll
    for (int k = 0; k < 16; k++) {
      float a[4], bb[8];
      #pragma unroll
      for (int i = 0; i < 4; i++) a[i]  = As[k][ty * 4 + i];
      #pragma unroll
      for (int j = 0; j < 8; j++) bb[j] = Bs[k][tx * 8 + j];
      #pragma unroll
      for (int i = 0; i < 4; i++)
        #pragma unroll
        for (int j = 0; j < 8; j++) acc[i][j] += a[i] * bb[j];
    }
    __syncthreads();
  }
  #pragma unroll
  for (int i = 0; i < 4; i++) {
    int u = u0 + ty * 4 + i;
    if (u < UTOP) {
      float* orow = g_Upd + ((size_t)b * UTOP + u) * 512 + n0 + tx * 8;
      #pragma unroll
      for (int j = 0; j < 8; j++) orow[j] = acc[i][j];
    }
  }
}

// ---------------------------------------------------------------------------
// 10) Assemble output: out[b, l*512+d] = selected ? upd[rank,d] : vmean[d]
//     (output reshape is a raw memory reinterpretation of (L, D) context)
// ---------------------------------------------------------------------------
__global__ void assemble_kernel(float* __restrict__ out) {
  const int b = blockIdx.y, l = blockIdx.x;
  const int r = g_selrank[b * LSP + l];
  const float4* src = (r >= 0)
      ? (const float4*)(g_Upd + ((size_t)b * UTOP + r) * 512)
      : (const float4*)(g_Vmean + (size_t)b * 512);
  float4* dst = (float4*)(out + ((size_t)b * LSP + l) * 512);
  dst[threadIdx.x] = src[threadIdx.x];
}

// ---------------------------------------------------------------------------
// Launch
// ---------------------------------------------------------------------------
extern "C" void kernel_launch(void* const* d_in, const int* in_sizes, int n_in,
                              void* d_out, int out_size) {
  const float* in1 = (const float*)d_in[0];
  const float* in2 = (const float*)d_in[1];
  const float* Wq  = (const float*)d_in[2];
  const float* bq  = (const float*)d_in[3];
  const float* Wk  = (const float*)d_in[4];
  const float* bk  = (const float*)d_in[5];
  const float* Wv  = (const float*)d_in[6];
  const float* bv  = (const float*)d_in[7];
  const int*   idx = (const int*)d_in[8];
  float* out = (float*)d_out;

  proj_kernel<<<dim3(32, 12, BATCH), 256>>>(in1, in2, Wq, bq, Wk, bk, Wv, bv);
  gather_ks_kernel<<<dim3(UTOP, BATCH), 128>>>(idx);
  qks_m_kernel<<<dim3(32, BATCH), 256>>>();
  topk_kernel<<<BATCH, 1024>>>();
  gather_qr_kernel<<<dim3(UTOP, BATCH), 128>>>();
  scores_kernel<<<dim3(32, 8, BATCH), 256>>>();
  softmax_kernel<<<BATCH * UTOP, 256>>>();
  vpart_kernel<<<dim3(4, BATCH), 512>>>();
  vmean_kernel<<<BATCH, 512>>>();
  upd_kernel<<<dim3(4, 8, BATCH), 256>>>();
  assemble_kernel<<<dim3(LSP, BATCH), 128>>>(out);
}

// round 2
// speedup vs baseline: 1.1379x; 1.1379x over previous
#include <cuda_runtime.h>
#include <math.h>

// Problem constants (fixed shapes per setup_inputs)
#define BATCH 16
#define CIN   256
#define CTOT  512
#define DDIM  512
#define LSP   4096
#define UTOP  450
#define SCALE 0.044194173824159216f   // 1/sqrt(512)

// ---------------------------------------------------------------------------
// Scratch (device globals: allocation inside kernel_launch is forbidden)
// ---------------------------------------------------------------------------
__device__ float g_QKV[BATCH * 3 * DDIM * LSP];      // [b][m in 0..1536)[sp]  (Q|K|V)
__device__ float g_Ks[BATCH * UTOP * DDIM];          // gathered K_sample rows
__device__ float g_M[BATCH * LSP];                   // sparsity measure
__device__ int   g_selrank[BATCH * LSP];             // l -> rank in top-k, or -1
__device__ int   g_mtop[BATCH * UTOP];               // rank -> l
__device__ float g_Qr[BATCH * UTOP * DDIM];          // gathered Q_reduce rows
__device__ float g_Scores[BATCH * UTOP * LSP];       // scores / attn (in place softmax)
__device__ float g_Upd[BATCH * UTOP * DDIM];         // attn @ V
__device__ float g_Vpart[BATCH * 4 * DDIM];          // partial V sums
__device__ float g_Vmean[BATCH * DDIM];              // V mean over L

// ---------------------------------------------------------------------------
// Fast exp: FFMA-only (no MUFU). x <= 0 expected (post max-subtraction).
// exp(x) = 2^(x*log2e); 2^f via degree-6 Taylor on f in [-0.5, 0.5].
// ---------------------------------------------------------------------------
__device__ __forceinline__ float fast_exp(float x) {
  x = fmaxf(x, -80.0f);
  float t = x * 1.4426950408889634f;
  float r = rintf(t);
  float f = t - r;
  float p = 1.5404e-4f;
  p = fmaf(p, f, 1.33336e-3f);
  p = fmaf(p, f, 9.61813e-3f);
  p = fmaf(p, f, 5.55041e-2f);
  p = fmaf(p, f, 2.40227e-1f);
  p = fmaf(p, f, 6.93147181e-1f);
  p = fmaf(p, f, 1.0f);
  return __int_as_float(__float_as_int(p) + (((int)r) << 23));
}

// ---------------------------------------------------------------------------
// 1) Projection GEMM: Y[b, m, sp] = sum_c W[m%512, c] * X[b, c, sp] + bias
//    128x128x16 tiles, 256 threads, 8x8/thread, double-buffered smem.
// ---------------------------------------------------------------------------
__global__ __launch_bounds__(256) void proj_kernel(
    const float* __restrict__ in1, const float* __restrict__ in2,
    const float* __restrict__ Wq, const float* __restrict__ bq,
    const float* __restrict__ Wk, const float* __restrict__ bk,
    const float* __restrict__ Wv, const float* __restrict__ bv) {
  const int b  = blockIdx.z;
  const int m0 = blockIdx.y * 128;
  const int n0 = blockIdx.x * 128;
  const int wsel = m0 >> 9;
  const float* W    = (wsel == 0) ? Wq : (wsel == 1) ? Wk : Wv;
  const float* bias = (wsel == 0) ? bq : (wsel == 1) ? bk : bv;
  const int mrow0 = m0 & 511;

  __shared__ float As[2][16][128];
  __shared__ float Bs[2][16][128];

  const int tid = threadIdx.x;
  const int tx = tid & 15, ty = tid >> 4;
  float acc[8][8] = {};

  const float* x1 = in1 + (size_t)b * CIN * LSP;
  const float* x2 = in2 + (size_t)b * CIN * LSP;

  // prologue: stage kt=0 directly into smem buffer 0
  #pragma unroll
  for (int i = 0; i < 2; i++) {
    int f = tid * 2 + i, m = f >> 2, kq = (f & 3) * 4;
    float4 v = *(const float4*)(W + (size_t)(mrow0 + m) * 512 + kq);
    As[0][kq + 0][m] = v.x; As[0][kq + 1][m] = v.y;
    As[0][kq + 2][m] = v.z; As[0][kq + 3][m] = v.w;
  }
  #pragma unroll
  for (int i = 0; i < 2; i++) {
    int f = tid * 2 + i, k = f >> 5, nq = (f & 31) * 4;
    const float* src = (k < 256) ? (x1 + (size_t)k * LSP) : (x2 + (size_t)(k - 256) * LSP);
    *(float4*)&Bs[0][k][nq] = *(const float4*)(src + n0 + nq);
  }
  __syncthreads();

  int buf = 0;
  for (int kt = 0; kt < 512; kt += 16) {
    const int ktn = kt + 16;
    float4 ra[2], rb[2];
    if (ktn < 512) {
      #pragma unroll
      for (int i = 0; i < 2; i++) {
        int f = tid * 2 + i, m = f >> 2, kq = (f & 3) * 4;
        ra[i] = *(const float4*)(W + (size_t)(mrow0 + m) * 512 + ktn + kq);
      }
      #pragma unroll
      for (int i = 0; i < 2; i++) {
        int f = tid * 2 + i, k = f >> 5, nq = (f & 31) * 4;
        int c = ktn + k;
        const float* src = (c < 256) ? (x1 + (size_t)c * LSP) : (x2 + (size_t)(c - 256) * LSP);
        rb[i] = *(const float4*)(src + n0 + nq);
      }
    }
    #pragma unroll
    for (int k = 0; k < 16; k++) {
      float a[8], bb[8];
      *(float4*)&a[0]  = *(const float4*)&As[buf][k][ty * 8];
      *(float4*)&a[4]  = *(const float4*)&As[buf][k][ty * 8 + 4];
      *(float4*)&bb[0] = *(const float4*)&Bs[buf][k][tx * 8];
      *(float4*)&bb[4] = *(const float4*)&Bs[buf][k][tx * 8 + 4];
      #pragma unroll
      for (int i = 0; i < 8; i++)
        #pragma unroll
        for (int j = 0; j < 8; j++) acc[i][j] = fmaf(a[i], bb[j], acc[i][j]);
    }
    if (ktn < 512) {
      #pragma unroll
      for (int i = 0; i < 2; i++) {
        int f = tid * 2 + i, m = f >> 2, kq = (f & 3) * 4;
        As[buf ^ 1][kq + 0][m] = ra[i].x; As[buf ^ 1][kq + 1][m] = ra[i].y;
        As[buf ^ 1][kq + 2][m] = ra[i].z; As[buf ^ 1][kq + 3][m] = ra[i].w;
      }
      #pragma unroll
      for (int i = 0; i < 2; i++) {
        int f = tid * 2 + i, k = f >> 5, nq = (f & 31) * 4;
        *(float4*)&Bs[buf ^ 1][k][nq] = rb[i];
      }
      __syncthreads();
      buf ^= 1;
    }
  }

  float* out = g_QKV + (size_t)b * 3 * DDIM * LSP;
  #pragma unroll
  for (int i = 0; i < 8; i++) {
    float bval = bias[mrow0 + ty * 8 + i];
    float* orow = out + (size_t)(m0 + ty * 8 + i) * LSP + n0 + tx * 8;
    #pragma unroll
    for (int j = 0; j < 8; j++) orow[j] = acc[i][j] + bval;
  }
}

// ---------------------------------------------------------------------------
// 2) Gather K_sample rows (K viewed as (L, D) from flat d-major buffer)
// ---------------------------------------------------------------------------
__global__ void gather_ks_kernel(const int* __restrict__ idx) {
  const int b = blockIdx.y, s = blockIdx.x;
  const int l = idx[s];
  const float4* src = (const float4*)(g_QKV + (size_t)b * 3 * DDIM * LSP
                                      + (size_t)DDIM * LSP + (size_t)l * 512);
  float4* dst = (float4*)(g_Ks + ((size_t)b * UTOP + s) * 512);
  dst[threadIdx.x] = src[threadIdx.x];   // 128 threads x float4 = 512 floats
}

// ---------------------------------------------------------------------------
// 3) Fused QKs + M:  M[l] = max_s dot(Q[l],Ks[s]) - (sum_s dot)/4096
//    128 l-rows x 128 s-cols tiles (s padded to 512, masked), double-buffered.
// ---------------------------------------------------------------------------
__global__ __launch_bounds__(256) void qks_m_kernel() {
  const int b  = blockIdx.y;
  const int l0 = blockIdx.x * 128;
  const float* Qb = g_QKV + (size_t)b * 3 * DDIM * LSP;   // Q rows: Qb + l*512
  const float* Ks = g_Ks + (size_t)b * UTOP * DDIM;

  __shared__ float As[2][16][128];
  __shared__ float Bs[2][16][128];

  const int tid = threadIdx.x;
  const int tx = tid & 15, ty = tid >> 4;
  float rmax[8], rsum[8];
  #pragma unroll
  for (int i = 0; i < 8; i++) { rmax[i] = -3.0e38f; rsum[i] = 0.f; }

  for (int s0 = 0; s0 < 512; s0 += 128) {
    float acc[8][8] = {};
    // prologue
    #pragma unroll
    for (int i = 0; i < 2; i++) {
      int f = tid * 2 + i, m = f >> 2, kq = (f & 3) * 4;
      float4 v = *(const float4*)(Qb + (size_t)(l0 + m) * 512 + kq);
      As[0][kq + 0][m] = v.x; As[0][kq + 1][m] = v.y;
      As[0][kq + 2][m] = v.z; As[0][kq + 3][m] = v.w;
    }
    #pragma unroll
    for (int i = 0; i < 2; i++) {
      int f = tid * 2 + i, n = f >> 2, kq = (f & 3) * 4;
      int row = s0 + n; if (row > UTOP - 1) row = UTOP - 1;
      float4 v = *(const float4*)(Ks + (size_t)row * 512 + kq);
      Bs[0][kq + 0][n] = v.x; Bs[0][kq + 1][n] = v.y;
      Bs[0][kq + 2][n] = v.z; Bs[0][kq + 3][n] = v.w;
    }
    __syncthreads();

    int buf = 0;
    for (int kt = 0; kt < 512; kt += 16) {
      const int ktn = kt + 16;
      float4 ra[2], rb[2];
      if (ktn < 512) {
        #pragma unroll
        for (int i = 0; i < 2; i++) {
          int f = tid * 2 + i, m = f >> 2, kq = (f & 3) * 4;
          ra[i] = *(const float4*)(Qb + (size_t)(l0 + m) * 512 + ktn + kq);
        }
        #pragma unroll
        for (int i = 0; i < 2; i++) {
          int f = tid * 2 + i, n = f >> 2, kq = (f & 3) * 4;
          int row = s0 + n; if (row > UTOP - 1) row = UTOP - 1;
          rb[i] = *(const float4*)(Ks + (size_t)row * 512 + ktn + kq);
        }
      }
      #pragma unroll
      for (int k = 0; k < 16; k++) {
        float a[8], bb[8];
        *(float4*)&a[0]  = *(const float4*)&As[buf][k][ty * 8];
        *(float4*)&a[4]  = *(const float4*)&As[buf][k][ty * 8 + 4];
        *(float4*)&bb[0] = *(const float4*)&Bs[buf][k][tx * 8];
        *(float4*)&bb[4] = *(const float4*)&Bs[buf][k][tx * 8 + 4];
        #pragma unroll
        for (int i = 0; i < 8; i++)
          #pragma unroll
          for (int j = 0; j < 8; j++) acc[i][j] = fmaf(a[i], bb[j], acc[i][j]);
      }
      if (ktn < 512) {
        #pragma unroll
        for (int i = 0; i < 2; i++) {
          int f = tid * 2 + i, m = f >> 2, kq = (f & 3) * 4;
          As[buf ^ 1][kq + 0][m] = ra[i].x; As[buf ^ 1][kq + 1][m] = ra[i].y;
          As[buf ^ 1][kq + 2][m] = ra[i].z; As[buf ^ 1][kq + 3][m] = ra[i].w;
        }
        #pragma unroll
        for (int i = 0; i < 2; i++) {
          int f = tid * 2 + i, n = f >> 2, kq = (f & 3) * 4;
          Bs[buf ^ 1][kq + 0][n] = rb[i].x; Bs[buf ^ 1][kq + 1][n] = rb[i].y;
          Bs[buf ^ 1][kq + 2][n] = rb[i].z; Bs[buf ^ 1][kq + 3][n] = rb[i].w;
        }
        __syncthreads();
        buf ^= 1;
      }
    }
    #pragma unroll
    for (int j = 0; j < 8; j++) {
      if (s0 + tx * 8 + j < UTOP) {
        #pragma unroll
        for (int i = 0; i < 8; i++) {
          rmax[i] = fmaxf(rmax[i], acc[i][j]);
          rsum[i] += acc[i][j];
        }
      }
    }
    __syncthreads();  // before re-staging prologue into buffer 0
  }
  // reduce across the 16 tx lanes
  #pragma unroll
  for (int off = 8; off; off >>= 1) {
    #pragma unroll
    for (int i = 0; i < 8; i++) {
      rmax[i] = fmaxf(rmax[i], __shfl_xor_sync(0xffffffffu, rmax[i], off));
      rsum[i] += __shfl_xor_sync(0xffffffffu, rsum[i], off);
    }
  }
  if (tx == 0) {
    #pragma unroll
    for (int i = 0; i < 8; i++)
      g_M[b * LSP + l0 + ty * 8 + i] = rmax[i] - rsum[i] * (1.0f / 4096.0f);
  }
}

// ---------------------------------------------------------------------------
// 4) Top-k via per-batch bitonic sort of 4096 64-bit keys (ties: lower idx)
// ---------------------------------------------------------------------------
__global__ __launch_bounds__(1024) void topk_kernel() {
  const int b = blockIdx.x;
  __shared__ unsigned long long keys[4096];
  const int tid = threadIdx.x;

  for (int i = tid; i < 4096; i += 1024) {
    unsigned u = __float_as_uint(g_M[b * LSP + i]);
    u = (u & 0x80000000u) ? ~u : (u | 0x80000000u);
    keys[i] = ((unsigned long long)(~u) << 32) | (unsigned)i;
  }
  __syncthreads();

  for (int k = 2; k <= 4096; k <<= 1) {
    for (int j = k >> 1; j > 0; j >>= 1) {
      for (int t = tid; t < 4096; t += 1024) {
        int ixj = t ^ j;
        if (ixj > t) {
          unsigned long long a = keys[t], c = keys[ixj];
          bool up = ((t & k) == 0);
          if ((a > c) == up) { keys[t] = c; keys[ixj] = a; }
        }
      }
      __syncthreads();
    }
  }

  for (int i = tid; i < 4096; i += 1024) g_selrank[b * LSP + i] = -1;
  __syncthreads();
  if (tid < UTOP) {
    int l = (int)(unsigned)(keys[tid] & 0xffffffffu);
    g_selrank[b * LSP + l] = tid;
    g_mtop[b * UTOP + tid] = l;
  }
}

// ---------------------------------------------------------------------------
// 5) Gather Q_reduce rows
// ---------------------------------------------------------------------------
__global__ void gather_qr_kernel() {
  const int b = blockIdx.y, u = blockIdx.x;
  const int l = g_mtop[b * UTOP + u];
  const float4* src = (const float4*)(g_QKV + (size_t)b * 3 * DDIM * LSP + (size_t)l * 512);
  float4* dst = (float4*)(g_Qr + ((size_t)b * UTOP + u) * 512);
  dst[threadIdx.x] = src[threadIdx.x];
}

// ---------------------------------------------------------------------------
// 6) scores[b,u,l] = SCALE * dot(Qr[u], K[l]);  128(u, padded) x 128(l) x 16
// ---------------------------------------------------------------------------
__global__ __launch_bounds__(256) void scores_kernel() {
  const int b  = blockIdx.z;
  const int u0 = blockIdx.y * 128;
  const int l0 = blockIdx.x * 128;
  const float* Qr = g_Qr + (size_t)b * UTOP * DDIM;
  const float* Kb = g_QKV + (size_t)b * 3 * DDIM * LSP + (size_t)DDIM * LSP;

  __shared__ float As[2][16][128];
  __shared__ float Bs[2][16][128];

  const int tid = threadIdx.x;
  const int tx = tid & 15, ty = tid >> 4;
  float acc[8][8] = {};

  #pragma unroll
  for (int i = 0; i < 2; i++) {
    int f = tid * 2 + i, m = f >> 2, kq = (f & 3) * 4;
    int row = u0 + m; if (row > UTOP - 1) row = UTOP - 1;
    float4 v = *(const float4*)(Qr + (size_t)row * 512 + kq);
    As[0][kq + 0][m] = v.x; As[0][kq + 1][m] = v.y;
    As[0][kq + 2][m] = v.z; As[0][kq + 3][m] = v.w;
  }
  #pragma unroll
  for (int i = 0; i < 2; i++) {
    int f = tid * 2 + i, n = f >> 2, kq = (f & 3) * 4;
    float4 v = *(const float4*)(Kb + (size_t)(l0 + n) * 512 + kq);
    Bs[0][kq + 0][n] = v.x; Bs[0][kq + 1][n] = v.y;
    Bs[0][kq + 2][n] = v.z; Bs[0][kq + 3][n] = v.w;
  }
  __syncthreads();

  int buf = 0;
  for (int kt = 0; kt < 512; kt += 16) {
    const int ktn = kt + 16;
    float4 ra[2], rb[2];
    if (ktn < 512) {
      #pragma unroll
      for (int i = 0; i < 2; i++) {
        int f = tid * 2 + i, m = f >> 2, kq = (f & 3) * 4;
        int row = u0 + m; if (row > UTOP - 1) row = UTOP - 1;
        ra[i] = *(const float4*)(Qr + (size_t)row * 512 + ktn + kq);
      }
      #pragma unroll
      for (int i = 0; i < 2; i++) {
        int f = tid * 2 + i, n = f >> 2, kq = (f & 3) * 4;
        rb[i] = *(const float4*)(Kb + (size_t)(l0 + n) * 512 + ktn + kq);
      }
    }
    #pragma unroll
    for (int k = 0; k < 16; k++) {
      float a[8], bb[8];
      *(float4*)&a[0]  = *(const float4*)&As[buf][k][ty * 8];
      *(float4*)&a[4]  = *(const float4*)&As[buf][k][ty * 8 + 4];
      *(float4*)&bb[0] = *(const float4*)&Bs[buf][k][tx * 8];
      *(float4*)&bb[4] = *(const float4*)&Bs[buf][k][tx * 8 + 4];
      #pragma unroll
      for (int i = 0; i < 8; i++)
        #pragma unroll
        for (int j = 0; j < 8; j++) acc[i][j] = fmaf(a[i], bb[j], acc[i][j]);
    }
    if (ktn < 512) {
      #pragma unroll
      for (int i = 0; i < 2; i++) {
        int f = tid * 2 + i, m = f >> 2, kq = (f & 3) * 4;
        As[buf ^ 1][kq + 0][m] = ra[i].x; As[buf ^ 1][kq + 1][m] = ra[i].y;
        As[buf ^ 1][kq + 2][m] = ra[i].z; As[buf ^ 1][kq + 3][m] = ra[i].w;
      }
      #pragma unroll
      for (int i = 0; i < 2; i++) {
        int f = tid * 2 + i, n = f >> 2, kq = (f & 3) * 4;
        Bs[buf ^ 1][kq + 0][n] = rb[i].x; Bs[buf ^ 1][kq + 1][n] = rb[i].y;
        Bs[buf ^ 1][kq + 2][n] = rb[i].z; Bs[buf ^ 1][kq + 3][n] = rb[i].w;
      }
      __syncthreads();
      buf ^= 1;
    }
  }
  #pragma unroll
  for (int i = 0; i < 8; i++) {
    int u = u0 + ty * 8 + i;
    if (u < UTOP) {
      float* orow = g_Scores + ((size_t)b * UTOP + u) * LSP + l0 + tx * 8;
      #pragma unroll
      for (int j = 0; j < 8; j++) orow[j] = acc[i][j] * SCALE;
    }
  }
}

// ---------------------------------------------------------------------------
// 7) Row softmax over 4096, in place (FFMA-only exp)
// ---------------------------------------------------------------------------
__global__ __launch_bounds__(256) void softmax_kernel() {
  const int row = blockIdx.x;             // b*UTOP + u
  float4* p = (float4*)(g_Scores + (size_t)row * LSP);
  const int tid = threadIdx.x;
  __shared__ float red[256];

  float4 r[4];
  float m = -3.0e38f;
  #pragma unroll
  for (int i = 0; i < 4; i++) {
    r[i] = p[tid + i * 256];
    m = fmaxf(m, fmaxf(fmaxf(r[i].x, r[i].y), fmaxf(r[i].z, r[i].w)));
  }
  red[tid] = m; __syncthreads();
  for (int s = 128; s; s >>= 1) {
    if (tid < s) red[tid] = fmaxf(red[tid], red[tid + s]);
    __syncthreads();
  }
  m = red[0]; __syncthreads();

  float sum = 0.f;
  #pragma unroll
  for (int i = 0; i < 4; i++) {
    r[i].x = fast_exp(r[i].x - m); r[i].y = fast_exp(r[i].y - m);
    r[i].z = fast_exp(r[i].z - m); r[i].w = fast_exp(r[i].w - m);
    sum += (r[i].x + r[i].y) + (r[i].z + r[i].w);
  }
  red[tid] = sum; __syncthreads();
  for (int s = 128; s; s >>= 1) {
    if (tid < s) red[tid] += red[tid + s];
    __syncthreads();
  }
  float inv = 1.0f / red[0];
  #pragma unroll
  for (int i = 0; i < 4; i++) {
    r[i].x *= inv; r[i].y *= inv; r[i].z *= inv; r[i].w *= inv;
    p[tid + i * 256] = r[i];
  }
}

// ---------------------------------------------------------------------------
// 8) V mean over L (two-stage, deterministic)
// ---------------------------------------------------------------------------
__global__ __launch_bounds__(512) void vpart_kernel() {
  const int b = blockIdx.y, g = blockIdx.x;   // g in [0,4)
  const int d = threadIdx.x;
  const float* Vb = g_QKV + (size_t)b * 3 * DDIM * LSP + 2 * (size_t)DDIM * LSP;
  const float* base = Vb + (size_t)(g * 1024) * 512 + d;
  float s0 = 0.f, s1 = 0.f, s2 = 0.f, s3 = 0.f;
  for (int l = 0; l < 1024; l += 4) {
    s0 += base[(size_t)(l + 0) * 512];
    s1 += base[(size_t)(l + 1) * 512];
    s2 += base[(size_t)(l + 2) * 512];
    s3 += base[(size_t)(l + 3) * 512];
  }
  g_Vpart[((size_t)b * 4 + g) * 512 + d] = (s0 + s1) + (s2 + s3);
}

__global__ __launch_bounds__(512) void vmean_kernel() {
  const int b = blockIdx.x, d = threadIdx.x;
  float s = 0.f;
  #pragma unroll
  for (int g = 0; g < 4; g++) s += g_Vpart[((size_t)b * 4 + g) * 512 + d];
  g_Vmean[b * 512 + d] = s * (1.0f / 4096.0f);
}

// ---------------------------------------------------------------------------
// 9) upd[b,u,d] = sum_l attn[u,l] * V[l,d];  128(u, padded) x 128(d) x 16, K=4096
// ---------------------------------------------------------------------------
__global__ __launch_bounds__(256) void upd_kernel() {
  const int b  = blockIdx.z;
  const int u0 = blockIdx.y * 128;
  const int n0 = blockIdx.x * 128;
  const float* At = g_Scores + (size_t)b * UTOP * LSP;  // attn rows, stride 4096
  const float* Vb = g_QKV + (size_t)b * 3 * DDIM * LSP + 2 * (size_t)DDIM * LSP;

  __shared__ float As[2][16][128];
  __shared__ float Bs[2][16][128];

  const int tid = threadIdx.x;
  const int tx = tid & 15, ty = tid >> 4;
  float acc[8][8] = {};

  #pragma unroll
  for (int i = 0; i < 2; i++) {
    int f = tid * 2 + i, m = f >> 2, kq = (f & 3) * 4;
    int row = u0 + m; if (row > UTOP - 1) row = UTOP - 1;
    float4 v = *(const float4*)(At + (size_t)row * LSP + kq);
    As[0][kq + 0][m] = v.x; As[0][kq + 1][m] = v.y;
    As[0][kq + 2][m] = v.z; As[0][kq + 3][m] = v.w;
  }
  #pragma unroll
  for (int i = 0; i < 2; i++) {
    int f = tid * 2 + i, k = f >> 5, nq = (f & 31) * 4;
    *(float4*)&Bs[0][k][nq] = *(const float4*)(Vb + (size_t)k * 512 + n0 + nq);
  }
  __syncthreads();

  int buf = 0;
  for (int kt = 0; kt < 4096; kt += 16) {
    const int ktn = kt + 16;
    float4 ra[2], rb[2];
    if (ktn < 4096) {
      #pragma unroll
      for (int i = 0; i < 2; i++) {
        int f = tid * 2 + i, m = f >> 2, kq = (f & 3) * 4;
        int row = u0 + m; if (row > UTOP - 1) row = UTOP - 1;
        ra[i] = *(const float4*)(At + (size_t)row * LSP + ktn + kq);
      }
      #pragma unroll
      for (int i = 0; i < 2; i++) {
        int f = tid * 2 + i, k = f >> 5, nq = (f & 31) * 4;
        rb[i] = *(const float4*)(Vb + (size_t)(ktn + k) * 512 + n0 + nq);
      }
    }
    #pragma unroll
    for (int k = 0; k < 16; k++) {
      float a[8], bb[8];
      *(float4*)&a[0]  = *(const float4*)&As[buf][k][ty * 8];
      *(float4*)&a[4]  = *(const float4*)&As[buf][k][ty * 8 + 4];
      *(float4*)&bb[0] = *(const float4*)&Bs[buf][k][tx * 8];
      *(float4*)&bb[4] = *(const float4*)&Bs[buf][k][tx * 8 + 4];
      #pragma unroll
      for (int i = 0; i < 8; i++)
        #pragma unroll
        for (int j = 0; j < 8; j++) acc[i][j] = fmaf(a[i], bb[j], acc[i][j]);
    }
    if (ktn < 4096) {
      #pragma unroll
      for (int i = 0; i < 2; i++) {
        int f = tid * 2 + i, m = f >> 2, kq = (f & 3) * 4;
        As[buf ^ 1][kq + 0][m] = ra[i].x; As[buf ^ 1][kq + 1][m] = ra[i].y;
        As[buf ^ 1][kq + 2][m] = ra[i].z; As[buf ^ 1][kq + 3][m] = ra[i].w;
      }
      #pragma unroll
      for (int i = 0; i < 2; i++) {
        int f = tid * 2 + i, k = f >> 5, nq = (f & 31) * 4;
        *(float4*)&Bs[buf ^ 1][k][nq] = rb[i];
      }
      __syncthreads();
      buf ^= 1;
    }
  }
  #pragma unroll
  for (int i = 0; i < 8; i++) {
    int u = u0 + ty * 8 + i;
    if (u < UTOP) {
      float* orow = g_Upd + ((size_t)b * UTOP + u) * 512 + n0 + tx * 8;
      #pragma unroll
      for (int j = 0; j < 8; j++) orow[j] = acc[i][j];
    }
  }
}

// ---------------------------------------------------------------------------
// 10) Assemble output
// ---------------------------------------------------------------------------
__global__ void assemble_kernel(float* __restrict__ out) {
  const int b = blockIdx.y, l = blockIdx.x;
  const int r = g_selrank[b * LSP + l];
  const float4* src = (r >= 0)
      ? (const float4*)(g_Upd + ((size_t)b * UTOP + r) * 512)
      : (const float4*)(g_Vmean + (size_t)b * 512);
  float4* dst = (float4*)(out + ((size_t)b * LSP + l) * 512);
  dst[threadIdx.x] = src[threadIdx.x];
}

// ---------------------------------------------------------------------------
// Launch
// ---------------------------------------------------------------------------
extern "C" void kernel_launch(void* const* d_in, const int* in_sizes, int n_in,
                              void* d_out, int out_size) {
  const float* in1 = (const float*)d_in[0];
  const float* in2 = (const float*)d_in[1];
  const float* Wq  = (const float*)d_in[2];
  const float* bq  = (const float*)d_in[3];
  const float* Wk  = (const float*)d_in[4];
  const float* bk  = (const float*)d_in[5];
  const float* Wv  = (const float*)d_in[6];
  const float* bv  = (const float*)d_in[7];
  const int*   idx = (const int*)d_in[8];
  float* out = (float*)d_out;

  proj_kernel<<<dim3(32, 12, BATCH), 256>>>(in1, in2, Wq, bq, Wk, bk, Wv, bv);
  gather_ks_kernel<<<dim3(UTOP, BATCH), 128>>>(idx);
  qks_m_kernel<<<dim3(32, BATCH), 256>>>();
  topk_kernel<<<BATCH, 1024>>>();
  gather_qr_kernel<<<dim3(UTOP, BATCH), 128>>>();
  scores_kernel<<<dim3(32, 4, BATCH), 256>>>();
  softmax_kernel<<<BATCH * UTOP, 256>>>();
  vpart_kernel<<<dim3(4, BATCH), 512>>>();
  vmean_kernel<<<BATCH, 512>>>();
  upd_kernel<<<dim3(4, 4, BATCH), 256>>>();
  assemble_kernel<<<dim3(LSP, BATCH), 128>>>(out);
}

// round 4
// speedup vs baseline: 1.1473x; 1.0083x over previous
#include <cuda_runtime.h>
#include <math.h>

// Problem constants (fixed shapes per setup_inputs)
#define BATCH 16
#define CIN   256
#define CTOT  512
#define DDIM  512
#define LSP   4096
#define UTOP  450
#define SCALE 0.044194173824159216f   // 1/sqrt(512)

// ---------------------------------------------------------------------------
// Scratch (device globals: allocation inside kernel_launch is forbidden)
// ---------------------------------------------------------------------------
__device__ float g_QKV[BATCH * 3 * DDIM * LSP];      // [b][m in 0..1536)[sp]  (Q|K|V)
__device__ float g_Ks[BATCH * UTOP * DDIM];          // gathered K_sample rows
__device__ float g_M[BATCH * LSP];                   // sparsity measure
__device__ int   g_selrank[BATCH * LSP];             // l -> rank in top-k, or -1
__device__ int   g_mtop[BATCH * UTOP];               // rank -> l
__device__ float g_Qr[BATCH * UTOP * DDIM];          // gathered Q_reduce rows
__device__ float g_Scores[BATCH * UTOP * LSP];       // scores / attn (in place softmax)
__device__ float g_Upd[BATCH * UTOP * DDIM];         // attn @ V
__device__ float g_Vpart[BATCH * 4 * DDIM];          // partial V sums
__device__ float g_Vmean[BATCH * DDIM];              // V mean over L

// ---------------------------------------------------------------------------
// Packed fp32x2 helpers (FFMA2 — 2x fp32 throughput, full precision)
// ---------------------------------------------------------------------------
__device__ __forceinline__ unsigned long long pack_dup(float x) {
  unsigned long long r;
  asm("mov.b64 %0, {%1, %1};" : "=l"(r) : "f"(x));
  return r;
}
__device__ __forceinline__ void ffma2(unsigned long long& d,
                                      unsigned long long a,
                                      unsigned long long b) {
  asm("fma.rn.f32x2 %0, %1, %2, %0;" : "+l"(d) : "l"(a), "l"(b));
}

// One 8x8 (as 8x4 packed) FFMA2 micro-tile step
#define MICRO_STEP(bufk_As, bufk_Bs)                                           \
  {                                                                            \
    float4 a0 = *(const float4*)&(bufk_As)[ty * 8];                            \
    float4 a1 = *(const float4*)&(bufk_As)[ty * 8 + 4];                        \
    ulonglong2 b01 = *(const ulonglong2*)&(bufk_Bs)[tx * 8];                   \
    ulonglong2 b23 = *(const ulonglong2*)&(bufk_Bs)[tx * 8 + 4];               \
    unsigned long long __align__(16) ap[8];                                    \
    ap[0] = pack_dup(a0.x); ap[1] = pack_dup(a0.y);                            \
    ap[2] = pack_dup(a0.z); ap[3] = pack_dup(a0.w);                            \
    ap[4] = pack_dup(a1.x); ap[5] = pack_dup(a1.y);                            \
    ap[6] = pack_dup(a1.z); ap[7] = pack_dup(a1.w);                            \
    _Pragma("unroll")                                                          \
    for (int i = 0; i < 8; i++) {                                              \
      ffma2(acc2[i][0], ap[i], b01.x);                                         \
      ffma2(acc2[i][1], ap[i], b01.y);                                         \
      ffma2(acc2[i][2], ap[i], b23.x);                                         \
      ffma2(acc2[i][3], ap[i], b23.y);                                         \
    }                                                                          \
  }

// ---------------------------------------------------------------------------
// Fast exp: FFMA-only (no MUFU). x <= 0 expected (post max-subtraction).
// ---------------------------------------------------------------------------
__device__ __forceinline__ float fast_exp(float x) {
  x = fmaxf(x, -80.0f);
  float t = x * 1.4426950408889634f;
  float r = rintf(t);
  float f = t - r;
  float p = 1.5404e-4f;
  p = fmaf(p, f, 1.33336e-3f);
  p = fmaf(p, f, 9.61813e-3f);
  p = fmaf(p, f, 5.55041e-2f);
  p = fmaf(p, f, 2.40227e-1f);
  p = fmaf(p, f, 6.93147181e-1f);
  p = fmaf(p, f, 1.0f);
  return __int_as_float(__float_as_int(p) + (((int)r) << 23));
}

// ---------------------------------------------------------------------------
// 1) Projection GEMM: Y[b, m, sp] = sum_c W[m%512, c] * X[b, c, sp] + bias
//    128x128x16 tiles, 256 threads, 8x8/thread (packed), double-buffered.
// ---------------------------------------------------------------------------
__global__ __launch_bounds__(256) void proj_kernel(
    const float* __restrict__ in1, const float* __restrict__ in2,
    const float* __restrict__ Wq, const float* __restrict__ bq,
    const float* __restrict__ Wk, const float* __restrict__ bk,
    const float* __restrict__ Wv, const float* __restrict__ bv) {
  const int b  = blockIdx.z;
  const int m0 = blockIdx.y * 128;
  const int n0 = blockIdx.x * 128;
  const int wsel = m0 >> 9;
  const float* W    = (wsel == 0) ? Wq : (wsel == 1) ? Wk : Wv;
  const float* bias = (wsel == 0) ? bq : (wsel == 1) ? bk : bv;
  const int mrow0 = m0 & 511;

  __shared__ float As[2][16][128];
  __shared__ float Bs[2][16][128];

  const int tid = threadIdx.x;
  const int tx = tid & 15, ty = tid >> 4;
  unsigned long long __align__(16) acc2[8][4] = {};

  const float* x1 = in1 + (size_t)b * CIN * LSP;
  const float* x2 = in2 + (size_t)b * CIN * LSP;

  #pragma unroll
  for (int i = 0; i < 2; i++) {
    int f = tid * 2 + i, m = f >> 2, kq = (f & 3) * 4;
    float4 v = *(const float4*)(W + (size_t)(mrow0 + m) * 512 + kq);
    As[0][kq + 0][m] = v.x; As[0][kq + 1][m] = v.y;
    As[0][kq + 2][m] = v.z; As[0][kq + 3][m] = v.w;
  }
  #pragma unroll
  for (int i = 0; i < 2; i++) {
    int f = tid * 2 + i, k = f >> 5, nq = (f & 31) * 4;
    const float* src = (k < 256) ? (x1 + (size_t)k * LSP) : (x2 + (size_t)(k - 256) * LSP);
    *(float4*)&Bs[0][k][nq] = *(const float4*)(src + n0 + nq);
  }
  __syncthreads();

  int buf = 0;
  for (int kt = 0; kt < 512; kt += 16) {
    const int ktn = kt + 16;
    float4 ra[2], rb[2];
    if (ktn < 512) {
      #pragma unroll
      for (int i = 0; i < 2; i++) {
        int f = tid * 2 + i, m = f >> 2, kq = (f & 3) * 4;
        ra[i] = *(const float4*)(W + (size_t)(mrow0 + m) * 512 + ktn + kq);
      }
      #pragma unroll
      for (int i = 0; i < 2; i++) {
        int f = tid * 2 + i, k = f >> 5, nq = (f & 31) * 4;
        int c = ktn + k;
        const float* src = (c < 256) ? (x1 + (size_t)c * LSP) : (x2 + (size_t)(c - 256) * LSP);
        rb[i] = *(const float4*)(src + n0 + nq);
      }
    }
    #pragma unroll
    for (int k = 0; k < 16; k++) MICRO_STEP(As[buf][k], Bs[buf][k]);
    if (ktn < 512) {
      #pragma unroll
      for (int i = 0; i < 2; i++) {
        int f = tid * 2 + i, m = f >> 2, kq = (f & 3) * 4;
        As[buf ^ 1][kq + 0][m] = ra[i].x; As[buf ^ 1][kq + 1][m] = ra[i].y;
        As[buf ^ 1][kq + 2][m] = ra[i].z; As[buf ^ 1][kq + 3][m] = ra[i].w;
      }
      #pragma unroll
      for (int i = 0; i < 2; i++) {
        int f = tid * 2 + i, k = f >> 5, nq = (f & 31) * 4;
        *(float4*)&Bs[buf ^ 1][k][nq] = rb[i];
      }
      __syncthreads();
      buf ^= 1;
    }
  }

  float* out = g_QKV + (size_t)b * 3 * DDIM * LSP;
  #pragma unroll
  for (int i = 0; i < 8; i++) {
    float bval = bias[mrow0 + ty * 8 + i];
    float* orow = out + (size_t)(m0 + ty * 8 + i) * LSP + n0 + tx * 8;
    #pragma unroll
    for (int jp = 0; jp < 4; jp++) {
      float2 v = *(float2*)&acc2[i][jp];
      v.x += bval; v.y += bval;
      *(float2*)(orow + jp * 2) = v;
    }
  }
}

// ---------------------------------------------------------------------------
// 2) Gather K_sample rows
// ---------------------------------------------------------------------------
__global__ void gather_ks_kernel(const int* __restrict__ idx) {
  const int b = blockIdx.y, s = blockIdx.x;
  const int l = idx[s];
  const float4* src = (const float4*)(g_QKV + (size_t)b * 3 * DDIM * LSP
                                      + (size_t)DDIM * LSP + (size_t)l * 512);
  float4* dst = (float4*)(g_Ks + ((size_t)b * UTOP + s) * 512);
  dst[threadIdx.x] = src[threadIdx.x];
}

// ---------------------------------------------------------------------------
// 3) Fused QKs + M:  M[l] = max_s dot(Q[l],Ks[s]) - (sum_s dot)/4096
// ---------------------------------------------------------------------------
__global__ __launch_bounds__(256) void qks_m_kernel() {
  const int b  = blockIdx.y;
  const int l0 = blockIdx.x * 128;
  const float* Qb = g_QKV + (size_t)b * 3 * DDIM * LSP;
  const float* Ks = g_Ks + (size_t)b * UTOP * DDIM;

  __shared__ float As[2][16][128];
  __shared__ float Bs[2][16][128];

  const int tid = threadIdx.x;
  const int tx = tid & 15, ty = tid >> 4;
  float rmax[8], rsum[8];
  #pragma unroll
  for (int i = 0; i < 8; i++) { rmax[i] = -3.0e38f; rsum[i] = 0.f; }

  for (int s0 = 0; s0 < 512; s0 += 128) {
    unsigned long long __align__(16) acc2[8][4] = {};
    #pragma unroll
    for (int i = 0; i < 2; i++) {
      int f = tid * 2 + i, m = f >> 2, kq = (f & 3) * 4;
      float4 v = *(const float4*)(Qb + (size_t)(l0 + m) * 512 + kq);
      As[0][kq + 0][m] = v.x; As[0][kq + 1][m] = v.y;
      As[0][kq + 2][m] = v.z; As[0][kq + 3][m] = v.w;
    }
    #pragma unroll
    for (int i = 0; i < 2; i++) {
      int f = tid * 2 + i, n = f >> 2, kq = (f & 3) * 4;
      int row = s0 + n; if (row > UTOP - 1) row = UTOP - 1;
      float4 v = *(const float4*)(Ks + (size_t)row * 512 + kq);
      Bs[0][kq + 0][n] = v.x; Bs[0][kq + 1][n] = v.y;
      Bs[0][kq + 2][n] = v.z; Bs[0][kq + 3][n] = v.w;
    }
    __syncthreads();

    int buf = 0;
    for (int kt = 0; kt < 512; kt += 16) {
      const int ktn = kt + 16;
      float4 ra[2], rb[2];
      if (ktn < 512) {
        #pragma unroll
        for (int i = 0; i < 2; i++) {
          int f = tid * 2 + i, m = f >> 2, kq = (f & 3) * 4;
          ra[i] = *(const float4*)(Qb + (size_t)(l0 + m) * 512 + ktn + kq);
        }
        #pragma unroll
        for (int i = 0; i < 2; i++) {
          int f = tid * 2 + i, n = f >> 2, kq = (f & 3) * 4;
          int row = s0 + n; if (row > UTOP - 1) row = UTOP - 1;
          rb[i] = *(const float4*)(Ks + (size_t)row * 512 + ktn + kq);
        }
      }
      #pragma unroll
      for (int k = 0; k < 16; k++) MICRO_STEP(As[buf][k], Bs[buf][k]);
      if (ktn < 512) {
        #pragma unroll
        for (int i = 0; i < 2; i++) {
          int f = tid * 2 + i, m = f >> 2, kq = (f & 3) * 4;
          As[buf ^ 1][kq + 0][m] = ra[i].x; As[buf ^ 1][kq + 1][m] = ra[i].y;
          As[buf ^ 1][kq + 2][m] = ra[i].z; As[buf ^ 1][kq + 3][m] = ra[i].w;
        }
        #pragma unroll
        for (int i = 0; i < 2; i++) {
          int f = tid * 2 + i, n = f >> 2, kq = (f & 3) * 4;
          Bs[buf ^ 1][kq + 0][n] = rb[i].x; Bs[buf ^ 1][kq + 1][n] = rb[i].y;
          Bs[buf ^ 1][kq + 2][n] = rb[i].z; Bs[buf ^ 1][kq + 3][n] = rb[i].w;
        }
        __syncthreads();
        buf ^= 1;
      }
    }
    #pragma unroll
    for (int jp = 0; jp < 4; jp++) {
      #pragma unroll
      for (int h = 0; h < 2; h++) {
        int j = jp * 2 + h;
        if (s0 + tx * 8 + j < UTOP) {
          #pragma unroll
          for (int i = 0; i < 8; i++) {
            float v = ((const float*)&acc2[i][jp])[h];
            rmax[i] = fmaxf(rmax[i], v);
            rsum[i] += v;
          }
        }
      }
    }
    __syncthreads();
  }
  #pragma unroll
  for (int off = 8; off; off >>= 1) {
    #pragma unroll
    for (int i = 0; i < 8; i++) {
      rmax[i] = fmaxf(rmax[i], __shfl_xor_sync(0xffffffffu, rmax[i], off));
      rsum[i] += __shfl_xor_sync(0xffffffffu, rsum[i], off);
    }
  }
  if (tx == 0) {
    #pragma unroll
    for (int i = 0; i < 8; i++)
      g_M[b * LSP + l0 + ty * 8 + i] = rmax[i] - rsum[i] * (1.0f / 4096.0f);
  }
}

// ---------------------------------------------------------------------------
// 4) Top-k via per-batch bitonic sort of 4096 64-bit keys (ties: lower idx)
// ---------------------------------------------------------------------------
__global__ __launch_bounds__(1024) void topk_kernel() {
  const int b = blockIdx.x;
  __shared__ unsigned long long keys[4096];
  const int tid = threadIdx.x;

  for (int i = tid; i < 4096; i += 1024) {
    unsigned u = __float_as_uint(g_M[b * LSP + i]);
    u = (u & 0x80000000u) ? ~u : (u | 0x80000000u);
    keys[i] = ((unsigned long long)(~u) << 32) | (unsigned)i;
  }
  __syncthreads();

  for (int k = 2; k <= 4096; k <<= 1) {
    for (int j = k >> 1; j > 0; j >>= 1) {
      for (int t = tid; t < 4096; t += 1024) {
        int ixj = t ^ j;
        if (ixj > t) {
          unsigned long long a = keys[t], c = keys[ixj];
          bool up = ((t & k) == 0);
          if ((a > c) == up) { keys[t] = c; keys[ixj] = a; }
        }
      }
      __syncthreads();
    }
  }

  for (int i = tid; i < 4096; i += 1024) g_selrank[b * LSP + i] = -1;
  __syncthreads();
  if (tid < UTOP) {
    int l = (int)(unsigned)(keys[tid] & 0xffffffffu);
    g_selrank[b * LSP + l] = tid;
    g_mtop[b * UTOP + tid] = l;
  }
}

// ---------------------------------------------------------------------------
// 5) Gather Q_reduce rows
// ---------------------------------------------------------------------------
__global__ void gather_qr_kernel() {
  const int b = blockIdx.y, u = blockIdx.x;
  const int l = g_mtop[b * UTOP + u];
  const float4* src = (const float4*)(g_QKV + (size_t)b * 3 * DDIM * LSP + (size_t)l * 512);
  float4* dst = (float4*)(g_Qr + ((size_t)b * UTOP + u) * 512);
  dst[threadIdx.x] = src[threadIdx.x];
}

// ---------------------------------------------------------------------------
// 6) scores[b,u,l] = SCALE * dot(Qr[u], K[l]);  128(u, padded) x 128(l) x 16
// ---------------------------------------------------------------------------
__global__ __launch_bounds__(256) void scores_kernel() {
  const int b  = blockIdx.z;
  const int u0 = blockIdx.y * 128;
  const int l0 = blockIdx.x * 128;
  const float* Qr = g_Qr + (size_t)b * UTOP * DDIM;
  const float* Kb = g_QKV + (size_t)b * 3 * DDIM * LSP + (size_t)DDIM * LSP;

  __shared__ float As[2][16][128];
  __shared__ float Bs[2][16][128];

  const int tid = threadIdx.x;
  const int tx = tid & 15, ty = tid >> 4;
  unsigned long long __align__(16) acc2[8][4] = {};

  #pragma unroll
  for (int i = 0; i < 2; i++) {
    int f = tid * 2 + i, m = f >> 2, kq = (f & 3) * 4;
    int row = u0 + m; if (row > UTOP - 1) row = UTOP - 1;
    float4 v = *(const float4*)(Qr + (size_t)row * 512 + kq);
    As[0][kq + 0][m] = v.x; As[0][kq + 1][m] = v.y;
    As[0][kq + 2][m] = v.z; As[0][kq + 3][m] = v.w;
  }
  #pragma unroll
  for (int i = 0; i < 2; i++) {
    int f = tid * 2 + i, n = f >> 2, kq = (f & 3) * 4;
    float4 v = *(const float4*)(Kb + (size_t)(l0 + n) * 512 + kq);
    Bs[0][kq + 0][n] = v.x; Bs[0][kq + 1][n] = v.y;
    Bs[0][kq + 2][n] = v.z; Bs[0][kq + 3][n] = v.w;
  }
  __syncthreads();

  int buf = 0;
  for (int kt = 0; kt < 512; kt += 16) {
    const int ktn = kt + 16;
    float4 ra[2], rb[2];
    if (ktn < 512) {
      #pragma unroll
      for (int i = 0; i < 2; i++) {
        int f = tid * 2 + i, m = f >> 2, kq = (f & 3) * 4;
        int row = u0 + m; if (row > UTOP - 1) row = UTOP - 1;
        ra[i] = *(const float4*)(Qr + (size_t)row * 512 + ktn + kq);
      }
      #pragma unroll
      for (int i = 0; i < 2; i++) {
        int f = tid * 2 + i, n = f >> 2, kq = (f & 3) * 4;
        rb[i] = *(const float4*)(Kb + (size_t)(l0 + n) * 512 + ktn + kq);
      }
    }
    #pragma unroll
    for (int k = 0; k < 16; k++) MICRO_STEP(As[buf][k], Bs[buf][k]);
    if (ktn < 512) {
      #pragma unroll
      for (int i = 0; i < 2; i++) {
        int f = tid * 2 + i, m = f >> 2, kq = (f & 3) * 4;
        As[buf ^ 1][kq + 0][m] = ra[i].x; As[buf ^ 1][kq + 1][m] = ra[i].y;
        As[buf ^ 1][kq + 2][m] = ra[i].z; As[buf ^ 1][kq + 3][m] = ra[i].w;
      }
      #pragma unroll
      for (int i = 0; i < 2; i++) {
        int f = tid * 2 + i, n = f >> 2, kq = (f & 3) * 4;
        Bs[buf ^ 1][kq + 0][n] = rb[i].x; Bs[buf ^ 1][kq + 1][n] = rb[i].y;
        Bs[buf ^ 1][kq + 2][n] = rb[i].z; Bs[buf ^ 1][kq + 3][n] = rb[i].w;
      }
      __syncthreads();
      buf ^= 1;
    }
  }
  #pragma unroll
  for (int i = 0; i < 8; i++) {
    int u = u0 + ty * 8 + i;
    if (u < UTOP) {
      float* orow = g_Scores + ((size_t)b * UTOP + u) * LSP + l0 + tx * 8;
      #pragma unroll
      for (int jp = 0; jp < 4; jp++) {
        float2 v = *(float2*)&acc2[i][jp];
        v.x *= SCALE; v.y *= SCALE;
        *(float2*)(orow + jp * 2) = v;
      }
    }
  }
}

// ---------------------------------------------------------------------------
// 7) Row softmax over 4096, in place (FFMA-only exp)
// ---------------------------------------------------------------------------
__global__ __launch_bounds__(256) void softmax_kernel() {
  const int row = blockIdx.x;
  float4* p = (float4*)(g_Scores + (size_t)row * LSP);
  const int tid = threadIdx.x;
  __shared__ float red[256];

  float4 r[4];
  float m = -3.0e38f;
  #pragma unroll
  for (int i = 0; i < 4; i++) {
    r[i] = p[tid + i * 256];
    m = fmaxf(m, fmaxf(fmaxf(r[i].x, r[i].y), fmaxf(r[i].z, r[i].w)));
  }
  red[tid] = m; __syncthreads();
  for (int s = 128; s; s >>= 1) {
    if (tid < s) red[tid] = fmaxf(red[tid], red[tid + s]);
    __syncthreads();
  }
  m = red[0]; __syncthreads();

  float sum = 0.f;
  #pragma unroll
  for (int i = 0; i < 4; i++) {
    r[i].x = fast_exp(r[i].x - m); r[i].y = fast_exp(r[i].y - m);
    r[i].z = fast_exp(r[i].z - m); r[i].w = fast_exp(r[i].w - m);
    sum += (r[i].x + r[i].y) + (r[i].z + r[i].w);
  }
  red[tid] = sum; __syncthreads();
  for (int s = 128; s; s >>= 1) {
    if (tid < s) red[tid] += red[tid + s];
    __syncthreads();
  }
  float inv = 1.0f / red[0];
  #pragma unroll
  for (int i = 0; i < 4; i++) {
    r[i].x *= inv; r[i].y *= inv; r[i].z *= inv; r[i].w *= inv;
    p[tid + i * 256] = r[i];
  }
}

// ---------------------------------------------------------------------------
// 8) V mean over L (two-stage, deterministic)
// ---------------------------------------------------------------------------
__global__ __launch_bounds__(512) void vpart_kernel() {
  const int b = blockIdx.y, g = blockIdx.x;
  const int d = threadIdx.x;
  const float* Vb = g_QKV + (size_t)b * 3 * DDIM * LSP + 2 * (size_t)DDIM * LSP;
  const float* base = Vb + (size_t)(g * 1024) * 512 + d;
  float s0 = 0.f, s1 = 0.f, s2 = 0.f, s3 = 0.f;
  for (int l = 0; l < 1024; l += 4) {
    s0 += base[(size_t)(l + 0) * 512];
    s1 += base[(size_t)(l + 1) * 512];
    s2 += base[(size_t)(l + 2) * 512];
    s3 += base[(size_t)(l + 3) * 512];
  }
  g_Vpart[((size_t)b * 4 + g) * 512 + d] = (s0 + s1) + (s2 + s3);
}

__global__ __launch_bounds__(512) void vmean_kernel() {
  const int b = blockIdx.x, d = threadIdx.x;
  float s = 0.f;
  #pragma unroll
  for (int g = 0; g < 4; g++) s += g_Vpart[((size_t)b * 4 + g) * 512 + d];
  g_Vmean[b * 512 + d] = s * (1.0f / 4096.0f);
}

// ---------------------------------------------------------------------------
// 9) upd[b,u,d] = sum_l attn[u,l] * V[l,d];  128(u, padded) x 128(d), K=4096
// ---------------------------------------------------------------------------
__global__ __launch_bounds__(256) void upd_kernel() {
  const int b  = blockIdx.z;
  const int u0 = blockIdx.y * 128;
  const int n0 = blockIdx.x * 128;
  const float* At = g_Scores + (size_t)b * UTOP * LSP;
  const float* Vb = g_QKV + (size_t)b * 3 * DDIM * LSP + 2 * (size_t)DDIM * LSP;

  __shared__ float As[2][16][128];
  __shared__ float Bs[2][16][128];

  const int tid = threadIdx.x;
  const int tx = tid & 15, ty = tid >> 4;
  unsigned long long __align__(16) acc2[8][4] = {};

  #pragma unroll
  for (int i = 0; i < 2; i++) {
    int f = tid * 2 + i, m = f >> 2, kq = (f & 3) * 4;
    int row = u0 + m; if (row > UTOP - 1) row = UTOP - 1;
    float4 v = *(const float4*)(At + (size_t)row * LSP + kq);
    As[0][kq + 0][m] = v.x; As[0][kq + 1][m] = v.y;
    As[0][kq + 2][m] = v.z; As[0][kq + 3][m] = v.w;
  }
  #pragma unroll
  for (int i = 0; i < 2; i++) {
    int f = tid * 2 + i, k = f >> 5, nq = (f & 31) * 4;
    *(float4*)&Bs[0][k][nq] = *(const float4*)(Vb + (size_t)k * 512 + n0 + nq);
  }
  __syncthreads();

  int buf = 0;
  for (int kt = 0; kt < 4096; kt += 16) {
    const int ktn = kt + 16;
    float4 ra[2], rb[2];
    if (ktn < 4096) {
      #pragma unroll
      for (int i = 0; i < 2; i++) {
        int f = tid * 2 + i, m = f >> 2, kq = (f & 3) * 4;
        int row = u0 + m; if (row > UTOP - 1) row = UTOP - 1;
        ra[i] = *(const float4*)(At + (size_t)row * LSP + ktn + kq);
      }
      #pragma unroll
      for (int i = 0; i < 2; i++) {
        int f = tid * 2 + i, k = f >> 5, nq = (f & 31) * 4;
        rb[i] = *(const float4*)(Vb + (size_t)(ktn + k) * 512 + n0 + nq);
      }
    }
    #pragma unroll
    for (int k = 0; k < 16; k++) MICRO_STEP(As[buf][k], Bs[buf][k]);
    if (ktn < 4096) {
      #pragma unroll
      for (int i = 0; i < 2; i++) {
        int f = tid * 2 + i, m = f >> 2, kq = (f & 3) * 4;
        As[buf ^ 1][kq + 0][m] = ra[i].x; As[buf ^ 1][kq + 1][m] = ra[i].y;
        As[buf ^ 1][kq + 2][m] = ra[i].z; As[buf ^ 1][kq + 3][m] = ra[i].w;
      }
      #pragma unroll
      for (int i = 0; i < 2; i++) {
        int f = tid * 2 + i, k = f >> 5, nq = (f & 31) * 4;
        *(float4*)&Bs[buf ^ 1][k][nq] = rb[i];
      }
      __syncthreads();
      buf ^= 1;
    }
  }
  #pragma unroll
  for (int i = 0; i < 8; i++) {
    int u = u0 + ty * 8 + i;
    if (u < UTOP) {
      float* orow = g_Upd + ((size_t)b * UTOP + u) * 512 + n0 + tx * 8;
      #pragma unroll
      for (int jp = 0; jp < 4; jp++)
        *(float2*)(orow + jp * 2) = *(float2*)&acc2[i][jp];
    }
  }
}

// ---------------------------------------------------------------------------
// 10) Assemble output
// ---------------------------------------------------------------------------
__global__ void assemble_kernel(float* __restrict__ out) {
  const int b = blockIdx.y, l = blockIdx.x;
  const int r = g_selrank[b * LSP + l];
  const float4* src = (r >= 0)
      ? (const float4*)(g_Upd + ((size_t)b * UTOP + r) * 512)
      : (const float4*)(g_Vmean + (size_t)b * 512);
  float4* dst = (float4*)(out + ((size_t)b * LSP + l) * 512);
  dst[threadIdx.x] = src[threadIdx.x];
}

// ---------------------------------------------------------------------------
// Launch
// ---------------------------------------------------------------------------
extern "C" void kernel_launch(void* const* d_in, const int* in_sizes, int n_in,
                              void* d_out, int out_size) {
  const float* in1 = (const float*)d_in[0];
  const float* in2 = (const float*)d_in[1];
  const float* Wq  = (const float*)d_in[2];
  const float* bq  = (const float*)d_in[3];
  const float* Wk  = (const float*)d_in[4];
  const float* bk  = (const float*)d_in[5];
  const float* Wv  = (const float*)d_in[6];
  const float* bv  = (const float*)d_in[7];
  const int*   idx = (const int*)d_in[8];
  float* out = (float*)d_out;

  proj_kernel<<<dim3(32, 12, BATCH), 256>>>(in1, in2, Wq, bq, Wk, bk, Wv, bv);
  gather_ks_kernel<<<dim3(UTOP, BATCH), 128>>>(idx);
  qks_m_kernel<<<dim3(32, BATCH), 256>>>();
  topk_kernel<<<BATCH, 1024>>>();
  gather_qr_kernel<<<dim3(UTOP, BATCH), 128>>>();
  scores_kernel<<<dim3(32, 4, BATCH), 256>>>();
  softmax_kernel<<<BATCH * UTOP, 256>>>();
  vpart_kernel<<<dim3(4, BATCH), 512>>>();
  vmean_kernel<<<BATCH, 512>>>();
  upd_kernel<<<dim3(4, 4, BATCH), 256>>>();
  assemble_kernel<<<dim3(LSP, BATCH), 128>>>(out);
}

// round 5
// speedup vs baseline: 1.1479x; 1.0005x over previous
#include <cuda_runtime.h>
#include <math.h>

// Problem constants (fixed shapes per setup_inputs)
#define BATCH 16
#define CIN   256
#define CTOT  512
#define DDIM  512
#define LSP   4096
#define UTOP  450
#define SCALE 0.044194173824159216f   // 1/sqrt(512)

// ---------------------------------------------------------------------------
// Scratch (device globals: allocation inside kernel_launch is forbidden)
// ---------------------------------------------------------------------------
__device__ float g_QKV[BATCH * 3 * DDIM * LSP];      // [b][m in 0..1536)[sp]  (Q|K|V)
__device__ float g_Ks[BATCH * UTOP * DDIM];          // gathered K_sample rows
__device__ float g_M[BATCH * LSP];                   // sparsity measure
__device__ int   g_selrank[BATCH * LSP];             // l -> rank in top-k, or -1
__device__ int   g_mtop[BATCH * UTOP];               // rank -> l
__device__ float g_Qr[BATCH * UTOP * DDIM];          // gathered Q_reduce rows
__device__ float g_Scores[BATCH * UTOP * LSP];       // scores / attn (in place softmax)
__device__ float g_Upd[BATCH * UTOP * DDIM];         // attn @ V
__device__ float g_Vpart[BATCH * 4 * DDIM];          // partial V sums
__device__ float g_Vmean[BATCH * DDIM];              // V mean over L

// ---------------------------------------------------------------------------
// Packed fp32x2 helpers (FFMA2 — 2x fp32 throughput, full precision)
// ---------------------------------------------------------------------------
__device__ __forceinline__ unsigned long long pack_dup(float x) {
  unsigned long long r;
  asm("mov.b64 %0, {%1, %1};" : "=l"(r) : "f"(x));
  return r;
}
__device__ __forceinline__ void ffma2(unsigned long long& d,
                                      unsigned long long a,
                                      unsigned long long b) {
  asm("fma.rn.f32x2 %0, %1, %2, %0;" : "+l"(d) : "l"(a), "l"(b));
}

// One 8x8 (as 8x4 packed) FFMA2 micro-tile step
#define MICRO_STEP(bufk_As, bufk_Bs)                                           \
  {                                                                            \
    float4 a0 = *(const float4*)&(bufk_As)[ty * 8];                            \
    float4 a1 = *(const float4*)&(bufk_As)[ty * 8 + 4];                        \
    ulonglong2 b01 = *(const ulonglong2*)&(bufk_Bs)[tx * 8];                   \
    ulonglong2 b23 = *(const ulonglong2*)&(bufk_Bs)[tx * 8 + 4];               \
    unsigned long long __align__(16) ap[8];                                    \
    ap[0] = pack_dup(a0.x); ap[1] = pack_dup(a0.y);                            \
    ap[2] = pack_dup(a0.z); ap[3] = pack_dup(a0.w);                            \
    ap[4] = pack_dup(a1.x); ap[5] = pack_dup(a1.y);                            \
    ap[6] = pack_dup(a1.z); ap[7] = pack_dup(a1.w);                            \
    _Pragma("unroll")                                                          \
    for (int i = 0; i < 8; i++) {                                              \
      ffma2(acc2[i][0], ap[i], b01.x);                                         \
      ffma2(acc2[i][1], ap[i], b01.y);                                         \
      ffma2(acc2[i][2], ap[i], b23.x);                                         \
      ffma2(acc2[i][3], ap[i], b23.y);                                         \
    }                                                                          \
  }

// ---------------------------------------------------------------------------
// Fast exp: FFMA-only (no MUFU). x <= 0 expected (post max-subtraction).
// ---------------------------------------------------------------------------
__device__ __forceinline__ float fast_exp(float x) {
  x = fmaxf(x, -80.0f);
  float t = x * 1.4426950408889634f;
  float r = rintf(t);
  float f = t - r;
  float p = 1.5404e-4f;
  p = fmaf(p, f, 1.33336e-3f);
  p = fmaf(p, f, 9.61813e-3f);
  p = fmaf(p, f, 5.55041e-2f);
  p = fmaf(p, f, 2.40227e-1f);
  p = fmaf(p, f, 6.93147181e-1f);
  p = fmaf(p, f, 1.0f);
  return __int_as_float(__float_as_int(p) + (((int)r) << 23));
}

// ---------------------------------------------------------------------------
// 1) Projection GEMM: Y[b, m, sp] = sum_c W[m%512, c] * X[b, c, sp] + bias
//    128x128x16 tiles, 256 threads, 8x8/thread (packed), double-buffered.
// ---------------------------------------------------------------------------
__global__ __launch_bounds__(256) void proj_kernel(
    const float* __restrict__ in1, const float* __restrict__ in2,
    const float* __restrict__ Wq, const float* __restrict__ bq,
    const float* __restrict__ Wk, const float* __restrict__ bk,
    const float* __restrict__ Wv, const float* __restrict__ bv) {
  const int b  = blockIdx.z;
  const int m0 = blockIdx.y * 128;
  const int n0 = blockIdx.x * 128;
  const int wsel = m0 >> 9;
  const float* W    = (wsel == 0) ? Wq : (wsel == 1) ? Wk : Wv;
  const float* bias = (wsel == 0) ? bq : (wsel == 1) ? bk : bv;
  const int mrow0 = m0 & 511;

  __shared__ float As[2][16][128];
  __shared__ float Bs[2][16][128];

  const int tid = threadIdx.x;
  const int tx = tid & 15, ty = tid >> 4;
  unsigned long long __align__(16) acc2[8][4] = {};

  const float* x1 = in1 + (size_t)b * CIN * LSP;
  const float* x2 = in2 + (size_t)b * CIN * LSP;

  #pragma unroll
  for (int i = 0; i < 2; i++) {
    int f = tid * 2 + i, m = f >> 2, kq = (f & 3) * 4;
    float4 v = *(const float4*)(W + (size_t)(mrow0 + m) * 512 + kq);
    As[0][kq + 0][m] = v.x; As[0][kq + 1][m] = v.y;
    As[0][kq + 2][m] = v.z; As[0][kq + 3][m] = v.w;
  }
  #pragma unroll
  for (int i = 0; i < 2; i++) {
    int f = tid * 2 + i, k = f >> 5, nq = (f & 31) * 4;
    const float* src = (k < 256) ? (x1 + (size_t)k * LSP) : (x2 + (size_t)(k - 256) * LSP);
    *(float4*)&Bs[0][k][nq] = *(const float4*)(src + n0 + nq);
  }
  __syncthreads();

  int buf = 0;
  for (int kt = 0; kt < 512; kt += 16) {
    const int ktn = kt + 16;
    float4 ra[2], rb[2];
    if (ktn < 512) {
      #pragma unroll
      for (int i = 0; i < 2; i++) {
        int f = tid * 2 + i, m = f >> 2, kq = (f & 3) * 4;
        ra[i] = *(const float4*)(W + (size_t)(mrow0 + m) * 512 + ktn + kq);
      }
      #pragma unroll
      for (int i = 0; i < 2; i++) {
        int f = tid * 2 + i, k = f >> 5, nq = (f & 31) * 4;
        int c = ktn + k;
        const float* src = (c < 256) ? (x1 + (size_t)c * LSP) : (x2 + (size_t)(c - 256) * LSP);
        rb[i] = *(const float4*)(src + n0 + nq);
      }
    }
    #pragma unroll
    for (int k = 0; k < 16; k++) MICRO_STEP(As[buf][k], Bs[buf][k]);
    if (ktn < 512) {
      #pragma unroll
      for (int i = 0; i < 2; i++) {
        int f = tid * 2 + i, m = f >> 2, kq = (f & 3) * 4;
        As[buf ^ 1][kq + 0][m] = ra[i].x; As[buf ^ 1][kq + 1][m] = ra[i].y;
        As[buf ^ 1][kq + 2][m] = ra[i].z; As[buf ^ 1][kq + 3][m] = ra[i].w;
      }
      #pragma unroll
      for (int i = 0; i < 2; i++) {
        int f = tid * 2 + i, k = f >> 5, nq = (f & 31) * 4;
        *(float4*)&Bs[buf ^ 1][k][nq] = rb[i];
      }
      __syncthreads();
      buf ^= 1;
    }
  }

  float* out = g_QKV + (size_t)b * 3 * DDIM * LSP;
  #pragma unroll
  for (int i = 0; i < 8; i++) {
    float bval = bias[mrow0 + ty * 8 + i];
    float* orow = out + (size_t)(m0 + ty * 8 + i) * LSP + n0 + tx * 8;
    #pragma unroll
    for (int jp = 0; jp < 4; jp++) {
      float2 v = *(float2*)&acc2[i][jp];
      v.x += bval; v.y += bval;
      *(float2*)(orow + jp * 2) = v;
    }
  }
}

// ---------------------------------------------------------------------------
// 2) Gather K_sample rows
// ---------------------------------------------------------------------------
__global__ void gather_ks_kernel(const int* __restrict__ idx) {
  const int b = blockIdx.y, s = blockIdx.x;
  const int l = idx[s];
  const float4* src = (const float4*)(g_QKV + (size_t)b * 3 * DDIM * LSP
                                      + (size_t)DDIM * LSP + (size_t)l * 512);
  float4* dst = (float4*)(g_Ks + ((size_t)b * UTOP + s) * 512);
  dst[threadIdx.x] = src[threadIdx.x];
}

// ---------------------------------------------------------------------------
// 3) Fused QKs + M:  M[l] = max_s dot(Q[l],Ks[s]) - (sum_s dot)/4096
// ---------------------------------------------------------------------------
__global__ __launch_bounds__(256) void qks_m_kernel() {
  const int b  = blockIdx.y;
  const int l0 = blockIdx.x * 128;
  const float* Qb = g_QKV + (size_t)b * 3 * DDIM * LSP;
  const float* Ks = g_Ks + (size_t)b * UTOP * DDIM;

  __shared__ float As[2][16][128];
  __shared__ float Bs[2][16][128];

  const int tid = threadIdx.x;
  const int tx = tid & 15, ty = tid >> 4;
  float rmax[8], rsum[8];
  #pragma unroll
  for (int i = 0; i < 8; i++) { rmax[i] = -3.0e38f; rsum[i] = 0.f; }

  for (int s0 = 0; s0 < 512; s0 += 128) {
    unsigned long long __align__(16) acc2[8][4] = {};
    #pragma unroll
    for (int i = 0; i < 2; i++) {
      int f = tid * 2 + i, m = f >> 2, kq = (f & 3) * 4;
      float4 v = *(const float4*)(Qb + (size_t)(l0 + m) * 512 + kq);
      As[0][kq + 0][m] = v.x; As[0][kq + 1][m] = v.y;
      As[0][kq + 2][m] = v.z; As[0][kq + 3][m] = v.w;
    }
    #pragma unroll
    for (int i = 0; i < 2; i++) {
      int f = tid * 2 + i, n = f >> 2, kq = (f & 3) * 4;
      int row = s0 + n; if (row > UTOP - 1) row = UTOP - 1;
      float4 v = *(const float4*)(Ks + (size_t)row * 512 + kq);
      Bs[0][kq + 0][n] = v.x; Bs[0][kq + 1][n] = v.y;
      Bs[0][kq + 2][n] = v.z; Bs[0][kq + 3][n] = v.w;
    }
    __syncthreads();

    int buf = 0;
    for (int kt = 0; kt < 512; kt += 16) {
      const int ktn = kt + 16;
      float4 ra[2], rb[2];
      if (ktn < 512) {
        #pragma unroll
        for (int i = 0; i < 2; i++) {
          int f = tid * 2 + i, m = f >> 2, kq = (f & 3) * 4;
          ra[i] = *(const float4*)(Qb + (size_t)(l0 + m) * 512 + ktn + kq);
        }
        #pragma unroll
        for (int i = 0; i < 2; i++) {
          int f = tid * 2 + i, n = f >> 2, kq = (f & 3) * 4;
          int row = s0 + n; if (row > UTOP - 1) row = UTOP - 1;
          rb[i] = *(const float4*)(Ks + (size_t)row * 512 + ktn + kq);
        }
      }
      #pragma unroll
      for (int k = 0; k < 16; k++) MICRO_STEP(As[buf][k], Bs[buf][k]);
      if (ktn < 512) {
        #pragma unroll
        for (int i = 0; i < 2; i++) {
          int f = tid * 2 + i, m = f >> 2, kq = (f & 3) * 4;
          As[buf ^ 1][kq + 0][m] = ra[i].x; As[buf ^ 1][kq + 1][m] = ra[i].y;
          As[buf ^ 1][kq + 2][m] = ra[i].z; As[buf ^ 1][kq + 3][m] = ra[i].w;
        }
        #pragma unroll
        for (int i = 0; i < 2; i++) {
          int f = tid * 2 + i, n = f >> 2, kq = (f & 3) * 4;
          Bs[buf ^ 1][kq + 0][n] = rb[i].x; Bs[buf ^ 1][kq + 1][n] = rb[i].y;
          Bs[buf ^ 1][kq + 2][n] = rb[i].z; Bs[buf ^ 1][kq + 3][n] = rb[i].w;
        }
        __syncthreads();
        buf ^= 1;
      }
    }
    #pragma unroll
    for (int jp = 0; jp < 4; jp++) {
      #pragma unroll
      for (int h = 0; h < 2; h++) {
        int j = jp * 2 + h;
        if (s0 + tx * 8 + j < UTOP) {
          #pragma unroll
          for (int i = 0; i < 8; i++) {
            float v = ((const float*)&acc2[i][jp])[h];
            rmax[i] = fmaxf(rmax[i], v);
            rsum[i] += v;
          }
        }
      }
    }
    __syncthreads();
  }
  #pragma unroll
  for (int off = 8; off; off >>= 1) {
    #pragma unroll
    for (int i = 0; i < 8; i++) {
      rmax[i] = fmaxf(rmax[i], __shfl_xor_sync(0xffffffffu, rmax[i], off));
      rsum[i] += __shfl_xor_sync(0xffffffffu, rsum[i], off);
    }
  }
  if (tx == 0) {
    #pragma unroll
    for (int i = 0; i < 8; i++)
      g_M[b * LSP + l0 + ty * 8 + i] = rmax[i] - rsum[i] * (1.0f / 4096.0f);
  }
}

// ---------------------------------------------------------------------------
// 4) Top-k via per-batch bitonic sort of 4096 64-bit keys (ties: lower idx)
// ---------------------------------------------------------------------------
__global__ __launch_bounds__(1024) void topk_kernel() {
  const int b = blockIdx.x;
  __shared__ unsigned long long keys[4096];
  const int tid = threadIdx.x;

  for (int i = tid; i < 4096; i += 1024) {
    unsigned u = __float_as_uint(g_M[b * LSP + i]);
    u = (u & 0x80000000u) ? ~u : (u | 0x80000000u);
    keys[i] = ((unsigned long long)(~u) << 32) | (unsigned)i;
  }
  __syncthreads();

  for (int k = 2; k <= 4096; k <<= 1) {
    for (int j = k >> 1; j > 0; j >>= 1) {
      for (int t = tid; t < 4096; t += 1024) {
        int ixj = t ^ j;
        if (ixj > t) {
          unsigned long long a = keys[t], c = keys[ixj];
          bool up = ((t & k) == 0);
          if ((a > c) == up) { keys[t] = c; keys[ixj] = a; }
        }
      }
      __syncthreads();
    }
  }

  for (int i = tid; i < 4096; i += 1024) g_selrank[b * LSP + i] = -1;
  __syncthreads();
  if (tid < UTOP) {
    int l = (int)(unsigned)(keys[tid] & 0xffffffffu);
    g_selrank[b * LSP + l] = tid;
    g_mtop[b * UTOP + tid] = l;
  }
}

// ---------------------------------------------------------------------------
// 5) Gather Q_reduce rows
// ---------------------------------------------------------------------------
__global__ void gather_qr_kernel() {
  const int b = blockIdx.y, u = blockIdx.x;
  const int l = g_mtop[b * UTOP + u];
  const float4* src = (const float4*)(g_QKV + (size_t)b * 3 * DDIM * LSP + (size_t)l * 512);
  float4* dst = (float4*)(g_Qr + ((size_t)b * UTOP + u) * 512);
  dst[threadIdx.x] = src[threadIdx.x];
}

// ---------------------------------------------------------------------------
// 6) scores[b,u,l] = SCALE * dot(Qr[u], K[l]);  128(u, padded) x 128(l) x 16
// ---------------------------------------------------------------------------
__global__ __launch_bounds__(256) void scores_kernel() {
  const int b  = blockIdx.z;
  const int u0 = blockIdx.y * 128;
  const int l0 = blockIdx.x * 128;
  const float* Qr = g_Qr + (size_t)b * UTOP * DDIM;
  const float* Kb = g_QKV + (size_t)b * 3 * DDIM * LSP + (size_t)DDIM * LSP;

  __shared__ float As[2][16][128];
  __shared__ float Bs[2][16][128];

  const int tid = threadIdx.x;
  const int tx = tid & 15, ty = tid >> 4;
  unsigned long long __align__(16) acc2[8][4] = {};

  #pragma unroll
  for (int i = 0; i < 2; i++) {
    int f = tid * 2 + i, m = f >> 2, kq = (f & 3) * 4;
    int row = u0 + m; if (row > UTOP - 1) row = UTOP - 1;
    float4 v = *(const float4*)(Qr + (size_t)row * 512 + kq);
    As[0][kq + 0][m] = v.x; As[0][kq + 1][m] = v.y;
    As[0][kq + 2][m] = v.z; As[0][kq + 3][m] = v.w;
  }
  #pragma unroll
  for (int i = 0; i < 2; i++) {
    int f = tid * 2 + i, n = f >> 2, kq = (f & 3) * 4;
    float4 v = *(const float4*)(Kb + (size_t)(l0 + n) * 512 + kq);
    Bs[0][kq + 0][n] = v.x; Bs[0][kq + 1][n] = v.y;
    Bs[0][kq + 2][n] = v.z; Bs[0][kq + 3][n] = v.w;
  }
  __syncthreads();

  int buf = 0;
  for (int kt = 0; kt < 512; kt += 16) {
    const int ktn = kt + 16;
    float4 ra[2], rb[2];
    if (ktn < 512) {
      #pragma unroll
      for (int i = 0; i < 2; i++) {
        int f = tid * 2 + i, m = f >> 2, kq = (f & 3) * 4;
        int row = u0 + m; if (row > UTOP - 1) row = UTOP - 1;
        ra[i] = *(const float4*)(Qr + (size_t)row * 512 + ktn + kq);
      }
      #pragma unroll
      for (int i = 0; i < 2; i++) {
        int f = tid * 2 + i, n = f >> 2, kq = (f & 3) * 4;
        rb[i] = *(const float4*)(Kb + (size_t)(l0 + n) * 512 + ktn + kq);
      }
    }
    #pragma unroll
    for (int k = 0; k < 16; k++) MICRO_STEP(As[buf][k], Bs[buf][k]);
    if (ktn < 512) {
      #pragma unroll
      for (int i = 0; i < 2; i++) {
        int f = tid * 2 + i, m = f >> 2, kq = (f & 3) * 4;
        As[buf ^ 1][kq + 0][m] = ra[i].x; As[buf ^ 1][kq + 1][m] = ra[i].y;
        As[buf ^ 1][kq + 2][m] = ra[i].z; As[buf ^ 1][kq + 3][m] = ra[i].w;
      }
      #pragma unroll
      for (int i = 0; i < 2; i++) {
        int f = tid * 2 + i, n = f >> 2, kq = (f & 3) * 4;
        Bs[buf ^ 1][kq + 0][n] = rb[i].x; Bs[buf ^ 1][kq + 1][n] = rb[i].y;
        Bs[buf ^ 1][kq + 2][n] = rb[i].z; Bs[buf ^ 1][kq + 3][n] = rb[i].w;
      }
      __syncthreads();
      buf ^= 1;
    }
  }
  #pragma unroll
  for (int i = 0; i < 8; i++) {
    int u = u0 + ty * 8 + i;
    if (u < UTOP) {
      float* orow = g_Scores + ((size_t)b * UTOP + u) * LSP + l0 + tx * 8;
      #pragma unroll
      for (int jp = 0; jp < 4; jp++) {
        float2 v = *(float2*)&acc2[i][jp];
        v.x *= SCALE; v.y *= SCALE;
        *(float2*)(orow + jp * 2) = v;
      }
    }
  }
}

// ---------------------------------------------------------------------------
// 7) Row softmax over 4096, in place (FFMA-only exp)
// ---------------------------------------------------------------------------
__global__ __launch_bounds__(256) void softmax_kernel() {
  const int row = blockIdx.x;
  float4* p = (float4*)(g_Scores + (size_t)row * LSP);
  const int tid = threadIdx.x;
  __shared__ float red[256];

  float4 r[4];
  float m = -3.0e38f;
  #pragma unroll
  for (int i = 0; i < 4; i++) {
    r[i] = p[tid + i * 256];
    m = fmaxf(m, fmaxf(fmaxf(r[i].x, r[i].y), fmaxf(r[i].z, r[i].w)));
  }
  red[tid] = m; __syncthreads();
  for (int s = 128; s; s >>= 1) {
    if (tid < s) red[tid] = fmaxf(red[tid], red[tid + s]);
    __syncthreads();
  }
  m = red[0]; __syncthreads();

  float sum = 0.f;
  #pragma unroll
  for (int i = 0; i < 4; i++) {
    r[i].x = fast_exp(r[i].x - m); r[i].y = fast_exp(r[i].y - m);
    r[i].z = fast_exp(r[i].z - m); r[i].w = fast_exp(r[i].w - m);
    sum += (r[i].x + r[i].y) + (r[i].z + r[i].w);
  }
  red[tid] = sum; __syncthreads();
  for (int s = 128; s; s >>= 1) {
    if (tid < s) red[tid] += red[tid + s];
    __syncthreads();
  }
  float inv = 1.0f / red[0];
  #pragma unroll
  for (int i = 0; i < 4; i++) {
    r[i].x *= inv; r[i].y *= inv; r[i].z *= inv; r[i].w *= inv;
    p[tid + i * 256] = r[i];
  }
}

// ---------------------------------------------------------------------------
// 8) V mean over L (two-stage, deterministic)
// ---------------------------------------------------------------------------
__global__ __launch_bounds__(512) void vpart_kernel() {
  const int b = blockIdx.y, g = blockIdx.x;
  const int d = threadIdx.x;
  const float* Vb = g_QKV + (size_t)b * 3 * DDIM * LSP + 2 * (size_t)DDIM * LSP;
  const float* base = Vb + (size_t)(g * 1024) * 512 + d;
  float s0 = 0.f, s1 = 0.f, s2 = 0.f, s3 = 0.f;
  for (int l = 0; l < 1024; l += 4) {
    s0 += base[(size_t)(l + 0) * 512];
    s1 += base[(size_t)(l + 1) * 512];
    s2 += base[(size_t)(l + 2) * 512];
    s3 += base[(size_t)(l + 3) * 512];
  }
  g_Vpart[((size_t)b * 4 + g) * 512 + d] = (s0 + s1) + (s2 + s3);
}

__global__ __launch_bounds__(512) void vmean_kernel() {
  const int b = blockIdx.x, d = threadIdx.x;
  float s = 0.f;
  #pragma unroll
  for (int g = 0; g < 4; g++) s += g_Vpart[((size_t)b * 4 + g) * 512 + d];
  g_Vmean[b * 512 + d] = s * (1.0f / 4096.0f);
}

// ---------------------------------------------------------------------------
// 9) upd[b,u,d] = sum_l attn[u,l] * V[l,d];  128(u, padded) x 128(d), K=4096
// ---------------------------------------------------------------------------
__global__ __launch_bounds__(256) void upd_kernel() {
  const int b  = blockIdx.z;
  const int u0 = blockIdx.y * 128;
  const int n0 = blockIdx.x * 128;
  const float* At = g_Scores + (size_t)b * UTOP * LSP;
  const float* Vb = g_QKV + (size_t)b * 3 * DDIM * LSP + 2 * (size_t)DDIM * LSP;

  __shared__ float As[2][16][128];
  __shared__ float Bs[2][16][128];

  const int tid = threadIdx.x;
  const int tx = tid & 15, ty = tid >> 4;
  unsigned long long __align__(16) acc2[8][4] = {};

  #pragma unroll
  for (int i = 0; i < 2; i++) {
    int f = tid * 2 + i, m = f >> 2, kq = (f & 3) * 4;
    int row = u0 + m; if (row > UTOP - 1) row = UTOP - 1;
    float4 v = *(const float4*)(At + (size_t)row * LSP + kq);
    As[0][kq + 0][m] = v.x; As[0][kq + 1][m] = v.y;
    As[0][kq + 2][m] = v.z; As[0][kq + 3][m] = v.w;
  }
  #pragma unroll
  for (int i = 0; i < 2; i++) {
    int f = tid * 2 + i, k = f >> 5, nq = (f & 31) * 4;
    *(float4*)&Bs[0][k][nq] = *(const float4*)(Vb + (size_t)k * 512 + n0 + nq);
  }
  __syncthreads();

  int buf = 0;
  for (int kt = 0; kt < 4096; kt += 16) {
    const int ktn = kt + 16;
    float4 ra[2], rb[2];
    if (ktn < 4096) {
      #pragma unroll
      for (int i = 0; i < 2; i++) {
        int f = tid * 2 + i, m = f >> 2, kq = (f & 3) * 4;
        int row = u0 + m; if (row > UTOP - 1) row = UTOP - 1;
        ra[i] = *(const float4*)(At + (size_t)row * LSP + ktn + kq);
      }
      #pragma unroll
      for (int i = 0; i < 2; i++) {
        int f = tid * 2 + i, k = f >> 5, nq = (f & 31) * 4;
        rb[i] = *(const float4*)(Vb + (size_t)(ktn + k) * 512 + n0 + nq);
      }
    }
    #pragma unroll
    for (int k = 0; k < 16; k++) MICRO_STEP(As[buf][k], Bs[buf][k]);
    if (ktn < 4096) {
      #pragma unroll
      for (int i = 0; i < 2; i++) {
        int f = tid * 2 + i, m = f >> 2, kq = (f & 3) * 4;
        As[buf ^ 1][kq + 0][m] = ra[i].x; As[buf ^ 1][kq + 1][m] = ra[i].y;
        As[buf ^ 1][kq + 2][m] = ra[i].z; As[buf ^ 1][kq + 3][m] = ra[i].w;
      }
      #pragma unroll
      for (int i = 0; i < 2; i++) {
        int f = tid * 2 + i, k = f >> 5, nq = (f & 31) * 4;
        *(float4*)&Bs[buf ^ 1][k][nq] = rb[i];
      }
      __syncthreads();
      buf ^= 1;
    }
  }
  #pragma unroll
  for (int i = 0; i < 8; i++) {
    int u = u0 + ty * 8 + i;
    if (u < UTOP) {
      float* orow = g_Upd + ((size_t)b * UTOP + u) * 512 + n0 + tx * 8;
      #pragma unroll
      for (int jp = 0; jp < 4; jp++)
        *(float2*)(orow + jp * 2) = *(float2*)&acc2[i][jp];
    }
  }
}

// ---------------------------------------------------------------------------
// 10) Assemble output
// ---------------------------------------------------------------------------
__global__ void assemble_kernel(float* __restrict__ out) {
  const int b = blockIdx.y, l = blockIdx.x;
  const int r = g_selrank[b * LSP + l];
  const float4* src = (r >= 0)
      ? (const float4*)(g_Upd + ((size_t)b * UTOP + r) * 512)
      : (const float4*)(g_Vmean + (size_t)b * 512);
  float4* dst = (float4*)(out + ((size_t)b * LSP + l) * 512);
  dst[threadIdx.x] = src[threadIdx.x];
}

// ---------------------------------------------------------------------------
// Launch
// ---------------------------------------------------------------------------
extern "C" void kernel_launch(void* const* d_in, const int* in_sizes, int n_in,
                              void* d_out, int out_size) {
  const float* in1 = (const float*)d_in[0];
  const float* in2 = (const float*)d_in[1];
  const float* Wq  = (const float*)d_in[2];
  const float* bq  = (const float*)d_in[3];
  const float* Wk  = (const float*)d_in[4];
  const float* bk  = (const float*)d_in[5];
  const float* Wv  = (const float*)d_in[6];
  const float* bv  = (const float*)d_in[7];
  const int*   idx = (const int*)d_in[8];
  float* out = (float*)d_out;

  proj_kernel<<<dim3(32, 12, BATCH), 256>>>(in1, in2, Wq, bq, Wk, bk, Wv, bv);
  gather_ks_kernel<<<dim3(UTOP, BATCH), 128>>>(idx);
  qks_m_kernel<<<dim3(32, BATCH), 256>>>();
  topk_kernel<<<BATCH, 1024>>>();
  gather_qr_kernel<<<dim3(UTOP, BATCH), 128>>>();
  scores_kernel<<<dim3(32, 4, BATCH), 256>>>();
  softmax_kernel<<<BATCH * UTOP, 256>>>();
  vpart_kernel<<<dim3(4, BATCH), 512>>>();
  vmean_kernel<<<BATCH, 512>>>();
  upd_kernel<<<dim3(4, 4, BATCH), 256>>>();
  assemble_kernel<<<dim3(LSP, BATCH), 128>>>(out);
}